// round 1
// baseline (speedup 1.0000x reference)
#include <cuda_runtime.h>
#include <cstdint>

#define BZf 8
#define Nf 4096
#define CFf 64
#define NSf 1024
#define Kf 64

// ---------------- scratch (device globals; no allocation) ----------------
__device__ float g_W0f[67 * 64];
__device__ float g_b0f[64];
__device__ float g_W1f[64 * 64];
__device__ float g_b1f[64];
__device__ float g_W2f[64 * 128];
__device__ float g_b2f[128];
__device__ float g_pp[BZf * Nf];
__device__ float g_A[BZf * Nf * 64];          // 8 MB: per-point x·W0'[3:] + b0'
__device__ int   g_knn_idx[BZf * NSf * Kf];   // 2 MB
__device__ float g_knn_dist[BZf * NSf * Kf];  // 2 MB

// ---------------- fold BN into weights ----------------
__global__ void fold_kernel(const float* W0, const float* b0, const float* gg0, const float* be0,
                            const float* rm0, const float* rv0,
                            const float* W1, const float* b1, const float* gg1, const float* be1,
                            const float* rm1, const float* rv1,
                            const float* W2, const float* b2, const float* gg2, const float* be2,
                            const float* rm2, const float* rv2) {
    int t = blockIdx.x * blockDim.x + threadIdx.x;
    int stride = gridDim.x * blockDim.x;
    for (int i = t; i < 67 * 64; i += stride) {
        int c = i & 63;
        float s = gg0[c] / sqrtf(rv0[c] + 1e-5f);
        g_W0f[i] = W0[i] * s;
    }
    for (int c = t; c < 64; c += stride) {
        float s = gg0[c] / sqrtf(rv0[c] + 1e-5f);
        g_b0f[c] = (b0[c] - rm0[c]) * s + be0[c];
    }
    for (int i = t; i < 64 * 64; i += stride) {
        int c = i & 63;
        float s = gg1[c] / sqrtf(rv1[c] + 1e-5f);
        g_W1f[i] = W1[i] * s;
    }
    for (int c = t; c < 64; c += stride) {
        float s = gg1[c] / sqrtf(rv1[c] + 1e-5f);
        g_b1f[c] = (b1[c] - rm1[c]) * s + be1[c];
    }
    for (int i = t; i < 64 * 128; i += stride) {
        int c = i & 127;
        float s = gg2[c] / sqrtf(rv2[c] + 1e-5f);
        g_W2f[i] = W2[i] * s;
    }
    for (int c = t; c < 128; c += stride) {
        float s = gg2[c] / sqrtf(rv2[c] + 1e-5f);
        g_b2f[c] = (b2[c] - rm2[c]) * s + be2[c];
    }
}

// ---------------- per-point squared norms (exact order: (x2+y2)+z2) ----------------
__global__ void pp_kernel(const float* pos) {
    int i = blockIdx.x * blockDim.x + threadIdx.x;
    if (i >= BZf * Nf) return;
    float x = pos[i * 3], y = pos[i * 3 + 1], z = pos[i * 3 + 2];
    g_pp[i] = __fadd_rn(__fadd_rn(__fmul_rn(x, x), __fmul_rn(y, y)), __fmul_rn(z, z));
}

// ---------------- FPS: one block per batch, exact argmax-first semantics ----------------
__global__ __launch_bounds__(1024) void fps_kernel(const float* pos, float* sampled) {
    int b = blockIdx.x;
    int t = threadIdx.x;
    float px[4], py[4], pz[4], dist[4];
#pragma unroll
    for (int r = 0; r < 4; r++) {
        int i = t + (r << 10);
        const float* p = &pos[(b * Nf + i) * 3];
        px[r] = p[0]; py[r] = p[1]; pz[r] = p[2];
        dist[r] = 1e10f;
    }
    __shared__ unsigned long long red[32];
    __shared__ float scx, scy, scz;
    __shared__ int snext;
    if (t == 0) snext = 0;
    __syncthreads();
    for (int s = 0; s < NSf; s++) {
        int cur = snext;
        int rr = cur >> 10, tt = cur & 1023;
        if (t == tt) {
            scx = px[rr]; scy = py[rr]; scz = pz[rr];
            float* o = &sampled[(b * NSf + s) * 3];
            o[0] = px[rr]; o[1] = py[rr]; o[2] = pz[rr];
        }
        __syncthreads();
        float cx = scx, cy = scy, cz = scz;
        unsigned long long key = 0ull;
#pragma unroll
        for (int r = 0; r < 4; r++) {
            float dx = __fsub_rn(px[r], cx);
            float dy = __fsub_rn(py[r], cy);
            float dz = __fsub_rn(pz[r], cz);
            float d = __fadd_rn(__fadd_rn(__fmul_rn(dx, dx), __fmul_rn(dy, dy)), __fmul_rn(dz, dz));
            dist[r] = fminf(dist[r], d);
            unsigned int i = (unsigned int)(t + (r << 10));
            unsigned long long kk =
                ((unsigned long long)__float_as_uint(dist[r]) << 32) | (unsigned long long)(~i);
            key = (kk > key) ? kk : key;
        }
#pragma unroll
        for (int o = 16; o; o >>= 1) {
            unsigned long long ok = __shfl_down_sync(0xffffffffu, key, o);
            key = (ok > key) ? ok : key;
        }
        if ((t & 31) == 0) red[t >> 5] = key;
        __syncthreads();
        if (t < 32) {
            unsigned long long k2 = red[t];
#pragma unroll
            for (int o = 16; o; o >>= 1) {
                unsigned long long ok = __shfl_down_sync(0xffffffffu, k2, o);
                k2 = (ok > k2) ? ok : k2;
            }
            if (t == 0) snext = (int)(~((unsigned int)(k2 & 0xffffffffull)));
        }
        __syncthreads();
    }
}

// ---------------- precompute A = x . W0'[3:67] + b0' ----------------
__global__ __launch_bounds__(64) void precA_kernel(const float* x) {
    int row0 = blockIdx.x * 4;
    int c = threadIdx.x;
    __shared__ float sx[4][64];
#pragma unroll
    for (int r = 0; r < 4; r++) sx[r][c] = x[(row0 + r) * 64 + c];
    __syncthreads();
    float bv = g_b0f[c];
    float a0 = bv, a1 = bv, a2 = bv, a3 = bv;
#pragma unroll 8
    for (int i = 0; i < 64; i++) {
        float w = g_W0f[(3 + i) * 64 + c];
        a0 = fmaf(sx[0][i], w, a0);
        a1 = fmaf(sx[1][i], w, a1);
        a2 = fmaf(sx[2][i], w, a2);
        a3 = fmaf(sx[3][i], w, a3);
    }
    g_A[(row0 + 0) * 64 + c] = a0;
    g_A[(row0 + 1) * 64 + c] = a1;
    g_A[(row0 + 2) * 64 + c] = a2;
    g_A[(row0 + 3) * 64 + c] = a3;
}

// ---------------- kNN top-64 per centroid (exact top_k tie semantics) ----------------
__global__ __launch_bounds__(128) void knn_kernel(const float* pos, const float* sampled) {
    extern __shared__ unsigned char smem[];
    float* sd = (float*)smem;                                               // 4096 f
    unsigned long long* cand = (unsigned long long*)(smem + 4096 * 4);      // 4096 u64
    int* scnt = (int*)(smem + 4096 * 4 + 4096 * 8);                         // 6 ints
    __shared__ float cxs, cys, czs, sss;
    int g = blockIdx.x;
    int b = g >> 10;
    int t = threadIdx.x;
    if (t == 0) {
        float cx = sampled[g * 3], cy = sampled[g * 3 + 1], cz = sampled[g * 3 + 2];
        cxs = cx; cys = cy; czs = cz;
        sss = __fadd_rn(__fadd_rn(__fmul_rn(cx, cx), __fmul_rn(cy, cy)), __fmul_rn(cz, cz));
    }
    if (t < 6) scnt[t] = 0;
    __syncthreads();
    float sx = cxs, sy = cys, sz = czs, ss = sss;
    const float T0 = 0.18f, T1 = 0.25f, T2 = 0.35f, T3 = 0.55f;
    int c0 = 0, c1 = 0, c2 = 0, c3 = 0;
    const float* pb = &pos[b * Nf * 3];
    const float* ppb = &g_pp[b * Nf];
    for (int p = t; p < Nf; p += 128) {
        float X = pb[p * 3], Y = pb[p * 3 + 1], Z = pb[p * 3 + 2];
        float dot = __fadd_rn(__fadd_rn(__fmul_rn(sx, X), __fmul_rn(sy, Y)), __fmul_rn(sz, Z));
        float d2 = __fsub_rn(__fadd_rn(ss, ppb[p]), __fmul_rn(2.0f, dot));
        float d = sqrtf(fmaxf(d2, 0.0f));
        sd[p] = d;
        c0 += (d <= T0); c1 += (d <= T1); c2 += (d <= T2); c3 += (d <= T3);
    }
    atomicAdd(&scnt[0], c0);
    atomicAdd(&scnt[1], c1);
    atomicAdd(&scnt[2], c2);
    atomicAdd(&scnt[3], c3);
    __syncthreads();
    float thr;
    if (scnt[0] >= Kf) thr = T0;
    else if (scnt[1] >= Kf) thr = T1;
    else if (scnt[2] >= Kf) thr = T2;
    else if (scnt[3] >= Kf) thr = T3;
    else thr = 1e30f;
    for (int p = t; p < Nf; p += 128) {
        float d = sd[p];
        if (d <= thr) {
            int slot = atomicAdd(&scnt[5], 1);
            cand[slot] = ((unsigned long long)__float_as_uint(d) << 32) | (unsigned int)p;
        }
    }
    __syncthreads();
    int cnt = scnt[5];
    int P = 128;
    while (P < cnt) P <<= 1;
    for (int i = t; i < P; i += 128)
        if (i >= cnt) cand[i] = 0xffffffffffffffffull;
    __syncthreads();
    for (int k2 = 2; k2 <= P; k2 <<= 1) {
        for (int j = k2 >> 1; j > 0; j >>= 1) {
            for (int i = t; i < P; i += 128) {
                int ij = i ^ j;
                if (ij > i) {
                    unsigned long long a = cand[i], bb = cand[ij];
                    bool up = ((i & k2) == 0);
                    if ((a > bb) == up) { cand[i] = bb; cand[ij] = a; }
                }
            }
            __syncthreads();
        }
    }
    if (t < Kf) {
        unsigned long long key = cand[t];
        g_knn_idx[g * Kf + t] = (int)(key & 0xffffffffull);
        g_knn_dist[g * Kf + t] = __uint_as_float((unsigned int)(key >> 32));
    }
}

// ---------------- fused MLP (layers 1..3) + masked max-pool per centroid ----------------
#define AKS 66  // activation row stride ([c][k] layout), 2-way-conflict compromise
__global__ __launch_bounds__(128) void mlp_kernel(const float* pos, const float* sampled, float* out) {
    extern __shared__ unsigned char smem[];
    float* act1 = (float*)smem;            // 64*66
    float* act2 = act1 + 64 * AKS;         // 64*66
    float* sW1 = act2 + 64 * AKS;          // 4096  (16B aligned: 2*64*66*4 = 33792)
    float* sW2 = sW1 + 4096;               // 8192
    float* sB1 = sW2 + 8192;               // 64
    float* sB2 = sB1 + 64;                 // 128
    float* sdpx = sB2 + 128;               // 64
    float* sdpy = sdpx + 64;               // 64
    float* sdpz = sdpy + 64;               // 64
    int* sidx = (int*)(sdpz + 64);         // 64
    int* smask = sidx + 64;                // 64
    float* pmax = (float*)(smask + 64);    // 8*128

    int g = blockIdx.x;
    int b = g >> 10;
    int t = threadIdx.x;

    for (int i = t; i < 4096; i += 128) sW1[i] = g_W1f[i];
    for (int i = t; i < 8192; i += 128) sW2[i] = g_W2f[i];
    if (t < 64) sB1[t] = g_b1f[t];
    if (t < 128) sB2[t] = g_b2f[t];
    if (t < 64) {
        int idx = g_knn_idx[g * Kf + t];
        float d = g_knn_dist[g * Kf + t];
        const float* p = &pos[(b * Nf + idx) * 3];
        float ccx = sampled[g * 3], ccy = sampled[g * 3 + 1], ccz = sampled[g * 3 + 2];
        sdpx[t] = p[0] - ccx;
        sdpy[t] = p[1] - ccy;
        sdpz[t] = p[2] - ccz;
        sidx[t] = idx;
        smask[t] = (d <= 0.2f) ? 1 : 0;
    }
    __syncthreads();

    // layer 1 (input 67 -> 64): A already holds x-part + bias; add dp part.
    {
        int c = t & 63;
        float w0 = g_W0f[c], w1 = g_W0f[64 + c], w2 = g_W0f[128 + c];
        for (int e = t; e < 4096; e += 128) {
            int k = e >> 6;
            float a = g_A[(b * Nf + sidx[k]) * 64 + c];
            float z = fmaf(sdpx[k], w0, a);
            z = fmaf(sdpy[k], w1, z);
            z = fmaf(sdpz[k], w2, z);
            act1[c * AKS + k] = fmaxf(z, 0.0f);
        }
    }
    __syncthreads();

    // layer 2 (64 -> 64): thread tile 8k x 4c
    {
        int kg = t & 7, cg = t >> 3;  // cg 0..15
        int k0 = kg * 8, cc0 = cg * 4;
        float acc[8][4];
#pragma unroll
        for (int a = 0; a < 8; a++)
#pragma unroll
            for (int bq = 0; bq < 4; bq++) acc[a][bq] = 0.0f;
        for (int ci = 0; ci < 64; ci++) {
            const float* ar = &act1[ci * AKS + k0];
            float2 a01 = *(const float2*)&ar[0];
            float2 a23 = *(const float2*)&ar[2];
            float2 a45 = *(const float2*)&ar[4];
            float2 a67 = *(const float2*)&ar[6];
            float av[8] = {a01.x, a01.y, a23.x, a23.y, a45.x, a45.y, a67.x, a67.y};
            float4 w = *(const float4*)&sW1[ci * 64 + cc0];
            float wv[4] = {w.x, w.y, w.z, w.w};
#pragma unroll
            for (int kk = 0; kk < 8; kk++)
#pragma unroll
                for (int ccq = 0; ccq < 4; ccq++)
                    acc[kk][ccq] = fmaf(av[kk], wv[ccq], acc[kk][ccq]);
        }
#pragma unroll
        for (int ccq = 0; ccq < 4; ccq++) {
            float bb = sB1[cc0 + ccq];
#pragma unroll
            for (int kk = 0; kk < 8; kk++)
                act2[(cc0 + ccq) * AKS + k0 + kk] = fmaxf(acc[kk][ccq] + bb, 0.0f);
        }
    }
    __syncthreads();

    // layer 3 (64 -> 128) + masked max pool: thread tile 8k x 8c
    {
        int kg = t & 7, cg = t >> 3;  // cg 0..15 -> c0 0..120
        int k0 = kg * 8, cc0 = cg * 8;
        float acc[8][8];
#pragma unroll
        for (int a = 0; a < 8; a++)
#pragma unroll
            for (int bq = 0; bq < 8; bq++) acc[a][bq] = 0.0f;
        for (int ci = 0; ci < 64; ci++) {
            const float* ar = &act2[ci * AKS + k0];
            float2 a01 = *(const float2*)&ar[0];
            float2 a23 = *(const float2*)&ar[2];
            float2 a45 = *(const float2*)&ar[4];
            float2 a67 = *(const float2*)&ar[6];
            float av[8] = {a01.x, a01.y, a23.x, a23.y, a45.x, a45.y, a67.x, a67.y};
            float4 w0 = *(const float4*)&sW2[ci * 128 + cc0];
            float4 w1 = *(const float4*)&sW2[ci * 128 + cc0 + 4];
            float wv[8] = {w0.x, w0.y, w0.z, w0.w, w1.x, w1.y, w1.z, w1.w};
#pragma unroll
            for (int kk = 0; kk < 8; kk++)
#pragma unroll
                for (int ccq = 0; ccq < 8; ccq++)
                    acc[kk][ccq] = fmaf(av[kk], wv[ccq], acc[kk][ccq]);
        }
#pragma unroll
        for (int ccq = 0; ccq < 8; ccq++) {
            float bb = sB2[cc0 + ccq];
            float m = -1e8f;
#pragma unroll
            for (int kk = 0; kk < 8; kk++) {
                float h = fmaxf(acc[kk][ccq] + bb, 0.0f);
                float v = smask[k0 + kk] ? h : -1e8f;
                m = fmaxf(m, v);
            }
            pmax[kg * 128 + cc0 + ccq] = m;
        }
    }
    __syncthreads();
    if (t < 128) {
        float m = pmax[t];
#pragma unroll
        for (int q = 1; q < 8; q++) m = fmaxf(m, pmax[q * 128 + t]);
        out[g * 128 + t] = m;
    }
}

// ---------------- launch ----------------
extern "C" void kernel_launch(void* const* d_in, const int* in_sizes, int n_in,
                              void* d_out, int out_size) {
    (void)in_sizes; (void)n_in; (void)out_size;
    const float* x = (const float*)d_in[0];
    const float* pos = (const float*)d_in[1];
    const float* W0 = (const float*)d_in[2];
    const float* b0 = (const float*)d_in[3];
    const float* gg0 = (const float*)d_in[4];
    const float* be0 = (const float*)d_in[5];
    const float* rm0 = (const float*)d_in[6];
    const float* rv0 = (const float*)d_in[7];
    const float* W1 = (const float*)d_in[8];
    const float* b1 = (const float*)d_in[9];
    const float* gg1 = (const float*)d_in[10];
    const float* be1 = (const float*)d_in[11];
    const float* rm1 = (const float*)d_in[12];
    const float* rv1 = (const float*)d_in[13];
    const float* W2 = (const float*)d_in[14];
    const float* b2 = (const float*)d_in[15];
    const float* gg2 = (const float*)d_in[16];
    const float* be2 = (const float*)d_in[17];
    const float* rm2 = (const float*)d_in[18];
    const float* rv2 = (const float*)d_in[19];

    float* out = (float*)d_out;
    float* sampled = out + (size_t)BZf * NSf * 128;

    const int knn_smem = 4096 * 4 + 4096 * 8 + 32;                   // 49184
    const int mlp_smem = (64 * AKS * 2 + 4096 + 8192 + 64 + 128 + 64 * 5 + 1024) * 4;
    cudaFuncSetAttribute(knn_kernel, cudaFuncAttributeMaxDynamicSharedMemorySize, knn_smem);
    cudaFuncSetAttribute(mlp_kernel, cudaFuncAttributeMaxDynamicSharedMemorySize, mlp_smem);

    fold_kernel<<<32, 256>>>(W0, b0, gg0, be0, rm0, rv0,
                             W1, b1, gg1, be1, rm1, rv1,
                             W2, b2, gg2, be2, rm2, rv2);
    pp_kernel<<<(BZf * Nf + 255) / 256, 256>>>(pos);
    fps_kernel<<<BZf, 1024>>>(pos, sampled);
    precA_kernel<<<BZf * Nf / 4, 64>>>(x);
    knn_kernel<<<BZf * NSf, 128, knn_smem>>>(pos, sampled);
    mlp_kernel<<<BZf * NSf, 128, mlp_smem>>>(pos, sampled, out);
}

// round 2
// speedup vs baseline: 1.3119x; 1.3119x over previous
#include <cuda_runtime.h>
#include <cstdint>

#define BZf 8
#define Nf 4096
#define CFf 64
#define NSf 1024
#define Kf 64

// ---------------- scratch (device globals; no allocation) ----------------
__device__ float g_W0f[67 * 64];
__device__ float g_b0f[64];
__device__ float g_W1f[64 * 64];
__device__ float g_b1f[64];
__device__ float g_W2f[64 * 128];
__device__ float g_b2f[128];
__device__ float g_pp[BZf * Nf];
__device__ float g_A[BZf * Nf * 64];          // 8 MB: per-point x·W0'[3:] + b0'
__device__ int   g_knn_idx[BZf * NSf * Kf];   // 2 MB
__device__ float g_knn_dist[BZf * NSf * Kf];  // 2 MB

// ---------------- packed fp32x2 helpers (sm_103a FFMA2) ----------------
__device__ __forceinline__ void ffma2(unsigned long long& acc, unsigned long long a,
                                      unsigned long long b) {
    asm("fma.rn.f32x2 %0, %1, %2, %0;" : "+l"(acc) : "l"(a), "l"(b));
}
__device__ __forceinline__ unsigned long long dup2(float v) {
    unsigned long long r;
    unsigned int u = __float_as_uint(v);
    asm("mov.b64 %0, {%1, %1};" : "=l"(r) : "r"(u));
    return r;
}
__device__ __forceinline__ float2 unpack2(unsigned long long v) {
    float2 f;
    asm("mov.b64 {%0, %1}, %2;" : "=f"(f.x), "=f"(f.y) : "l"(v));
    return f;
}

// ---------------- fold BN into weights ----------------
__global__ void fold_kernel(const float* W0, const float* b0, const float* gg0, const float* be0,
                            const float* rm0, const float* rv0,
                            const float* W1, const float* b1, const float* gg1, const float* be1,
                            const float* rm1, const float* rv1,
                            const float* W2, const float* b2, const float* gg2, const float* be2,
                            const float* rm2, const float* rv2) {
    int t = blockIdx.x * blockDim.x + threadIdx.x;
    int stride = gridDim.x * blockDim.x;
    for (int i = t; i < 67 * 64; i += stride) {
        int c = i & 63;
        float s = gg0[c] / sqrtf(rv0[c] + 1e-5f);
        g_W0f[i] = W0[i] * s;
    }
    for (int c = t; c < 64; c += stride) {
        float s = gg0[c] / sqrtf(rv0[c] + 1e-5f);
        g_b0f[c] = (b0[c] - rm0[c]) * s + be0[c];
    }
    for (int i = t; i < 64 * 64; i += stride) {
        int c = i & 63;
        float s = gg1[c] / sqrtf(rv1[c] + 1e-5f);
        g_W1f[i] = W1[i] * s;
    }
    for (int c = t; c < 64; c += stride) {
        float s = gg1[c] / sqrtf(rv1[c] + 1e-5f);
        g_b1f[c] = (b1[c] - rm1[c]) * s + be1[c];
    }
    for (int i = t; i < 64 * 128; i += stride) {
        int c = i & 127;
        float s = gg2[c] / sqrtf(rv2[c] + 1e-5f);
        g_W2f[i] = W2[i] * s;
    }
    for (int c = t; c < 128; c += stride) {
        float s = gg2[c] / sqrtf(rv2[c] + 1e-5f);
        g_b2f[c] = (b2[c] - rm2[c]) * s + be2[c];
    }
}

// ---------------- per-point squared norms (exact order: (x2+y2)+z2) ----------------
__global__ void pp_kernel(const float* pos) {
    int i = blockIdx.x * blockDim.x + threadIdx.x;
    if (i >= BZf * Nf) return;
    float x = pos[i * 3], y = pos[i * 3 + 1], z = pos[i * 3 + 2];
    g_pp[i] = __fadd_rn(__fadd_rn(__fmul_rn(x, x), __fmul_rn(y, y)), __fmul_rn(z, z));
}

// ---------------- FPS: one block per batch, REDUX-based argmax (exact first-index tie) ---
__global__ __launch_bounds__(1024) void fps_kernel(const float* pos, float* sampled) {
    extern __shared__ unsigned char fsm[];
    float* spx = (float*)fsm;                 // 4096
    float* spy = spx + Nf;                    // 4096
    float* spz = spy + Nf;                    // 4096
    unsigned int* rd = (unsigned int*)(spz + Nf);  // 32
    unsigned int* ri = rd + 32;                    // 32
    float* sc = (float*)(ri + 32);                 // 3 (cx, cy, cz)

    int b = blockIdx.x;
    int t = threadIdx.x;
    float px[4], py[4], pz[4], dist[4];
#pragma unroll
    for (int r = 0; r < 4; r++) {
        int i = t + (r << 10);
        const float* p = &pos[(b * Nf + i) * 3];
        float X = p[0], Y = p[1], Z = p[2];
        px[r] = X; py[r] = Y; pz[r] = Z;
        spx[i] = X; spy[i] = Y; spz[i] = Z;
        dist[r] = 1e10f;
    }
    if (t == 0) {
        const float* p = &pos[b * Nf * 3];
        sc[0] = p[0]; sc[1] = p[1]; sc[2] = p[2];
        float* o = &sampled[b * NSf * 3];
        o[0] = p[0]; o[1] = p[1]; o[2] = p[2];
    }
    __syncthreads();

    for (int s = 0; s < NSf - 1; s++) {
        float cx = sc[0], cy = sc[1], cz = sc[2];
        unsigned int m;
        int bi;
        {
            float dx = __fsub_rn(px[0], cx);
            float dy = __fsub_rn(py[0], cy);
            float dz = __fsub_rn(pz[0], cz);
            float d = __fadd_rn(__fadd_rn(__fmul_rn(dx, dx), __fmul_rn(dy, dy)), __fmul_rn(dz, dz));
            dist[0] = fminf(dist[0], d);
            m = __float_as_uint(dist[0]);
            bi = t;
        }
#pragma unroll
        for (int r = 1; r < 4; r++) {
            float dx = __fsub_rn(px[r], cx);
            float dy = __fsub_rn(py[r], cy);
            float dz = __fsub_rn(pz[r], cz);
            float d = __fadd_rn(__fadd_rn(__fmul_rn(dx, dx), __fmul_rn(dy, dy)), __fmul_rn(dz, dz));
            dist[r] = fminf(dist[r], d);
            unsigned int bits = __float_as_uint(dist[r]);
            if (bits > m) { m = bits; bi = t + (r << 10); }
        }
        unsigned int wm = __reduce_max_sync(0xffffffffu, m);
        unsigned int cand = (m == wm) ? ~(unsigned int)bi : 0u;
        unsigned int wi = __reduce_max_sync(0xffffffffu, cand);
        if ((t & 31) == 0) { rd[t >> 5] = wm; ri[t >> 5] = wi; }
        __syncthreads();
        if (t < 32) {
            unsigned int d2 = rd[t], i2 = ri[t];
            unsigned int g = __reduce_max_sync(0xffffffffu, d2);
            unsigned int c2 = (d2 == g) ? i2 : 0u;
            unsigned int gi = __reduce_max_sync(0xffffffffu, c2);
            if (t == 0) {
                int nidx = (int)(~gi);
                float nx = spx[nidx], ny = spy[nidx], nz = spz[nidx];
                sc[0] = nx; sc[1] = ny; sc[2] = nz;
                float* o = &sampled[(b * NSf + s + 1) * 3];
                o[0] = nx; o[1] = ny; o[2] = nz;
            }
        }
        __syncthreads();
    }
}

// ---------------- precompute A = x . W0'[3:67] + b0' ----------------
__global__ __launch_bounds__(64) void precA_kernel(const float* x) {
    int row0 = blockIdx.x * 4;
    int c = threadIdx.x;
    __shared__ float sx[4][64];
#pragma unroll
    for (int r = 0; r < 4; r++) sx[r][c] = x[(row0 + r) * 64 + c];
    __syncthreads();
    float bv = g_b0f[c];
    float a0 = bv, a1 = bv, a2 = bv, a3 = bv;
#pragma unroll 8
    for (int i = 0; i < 64; i++) {
        float w = g_W0f[(3 + i) * 64 + c];
        a0 = fmaf(sx[0][i], w, a0);
        a1 = fmaf(sx[1][i], w, a1);
        a2 = fmaf(sx[2][i], w, a2);
        a3 = fmaf(sx[3][i], w, a3);
    }
    g_A[(row0 + 0) * 64 + c] = a0;
    g_A[(row0 + 1) * 64 + c] = a1;
    g_A[(row0 + 2) * 64 + c] = a2;
    g_A[(row0 + 3) * 64 + c] = a3;
}

// ---------------- kNN top-64 per centroid (exact top_k tie semantics) ----------------
__global__ __launch_bounds__(128) void knn_kernel(const float* pos, const float* sampled) {
    extern __shared__ unsigned char smem[];
    float* sd = (float*)smem;                                               // 4096 f
    unsigned long long* cand = (unsigned long long*)(smem + 4096 * 4);      // 4096 u64
    int* scnt = (int*)(smem + 4096 * 4 + 4096 * 8);                         // 6 ints
    __shared__ float cxs, cys, czs, sss;
    int g = blockIdx.x;
    int b = g >> 10;
    int t = threadIdx.x;
    if (t == 0) {
        float cx = sampled[g * 3], cy = sampled[g * 3 + 1], cz = sampled[g * 3 + 2];
        cxs = cx; cys = cy; czs = cz;
        sss = __fadd_rn(__fadd_rn(__fmul_rn(cx, cx), __fmul_rn(cy, cy)), __fmul_rn(cz, cz));
    }
    if (t < 6) scnt[t] = 0;
    __syncthreads();
    float sx = cxs, sy = cys, sz = czs, ss = sss;
    const float T0 = 0.18f, T1 = 0.25f, T2 = 0.35f, T3 = 0.55f;
    int c0 = 0, c1 = 0, c2 = 0, c3 = 0;
    const float* pb = &pos[b * Nf * 3];
    const float* ppb = &g_pp[b * Nf];
    for (int p = t; p < Nf; p += 128) {
        float X = pb[p * 3], Y = pb[p * 3 + 1], Z = pb[p * 3 + 2];
        float dot = __fadd_rn(__fadd_rn(__fmul_rn(sx, X), __fmul_rn(sy, Y)), __fmul_rn(sz, Z));
        float d2 = __fsub_rn(__fadd_rn(ss, ppb[p]), __fmul_rn(2.0f, dot));
        float d = sqrtf(fmaxf(d2, 0.0f));
        sd[p] = d;
        c0 += (d <= T0); c1 += (d <= T1); c2 += (d <= T2); c3 += (d <= T3);
    }
    atomicAdd(&scnt[0], c0);
    atomicAdd(&scnt[1], c1);
    atomicAdd(&scnt[2], c2);
    atomicAdd(&scnt[3], c3);
    __syncthreads();
    float thr;
    if (scnt[0] >= Kf) thr = T0;
    else if (scnt[1] >= Kf) thr = T1;
    else if (scnt[2] >= Kf) thr = T2;
    else if (scnt[3] >= Kf) thr = T3;
    else thr = 1e30f;
    for (int p = t; p < Nf; p += 128) {
        float d = sd[p];
        if (d <= thr) {
            int slot = atomicAdd(&scnt[5], 1);
            cand[slot] = ((unsigned long long)__float_as_uint(d) << 32) | (unsigned int)p;
        }
    }
    __syncthreads();
    int cnt = scnt[5];
    int P = 128;
    while (P < cnt) P <<= 1;
    for (int i = t; i < P; i += 128)
        if (i >= cnt) cand[i] = 0xffffffffffffffffull;
    __syncthreads();
    for (int k2 = 2; k2 <= P; k2 <<= 1) {
        for (int j = k2 >> 1; j > 0; j >>= 1) {
            for (int i = t; i < P; i += 128) {
                int ij = i ^ j;
                if (ij > i) {
                    unsigned long long a = cand[i], bb = cand[ij];
                    bool up = ((i & k2) == 0);
                    if ((a > bb) == up) { cand[i] = bb; cand[ij] = a; }
                }
            }
            __syncthreads();
        }
    }
    if (t < Kf) {
        unsigned long long key = cand[t];
        g_knn_idx[g * Kf + t] = (int)(key & 0xffffffffull);
        g_knn_dist[g * Kf + t] = __uint_as_float((unsigned int)(key >> 32));
    }
}

// ---------------- fused MLP (layers 1..3, FFMA2) + masked max-pool per centroid --------
#define AKS 66  // activation row stride ([c][k] layout), avoids 32-way store conflicts
__global__ __launch_bounds__(128) void mlp_kernel(const float* pos, const float* sampled, float* out) {
    extern __shared__ unsigned char smem[];
    float* act1 = (float*)smem;            // 64*66
    float* act2 = act1 + 64 * AKS;         // 64*66
    float* sW1 = act2 + 64 * AKS;          // 4096
    float* sW2 = sW1 + 4096;               // 8192
    float* sB1 = sW2 + 8192;               // 64
    float* sB2 = sB1 + 64;                 // 128
    float* sdpx = sB2 + 128;               // 64
    float* sdpy = sdpx + 64;               // 64
    float* sdpz = sdpy + 64;               // 64
    int* sidx = (int*)(sdpz + 64);         // 64
    int* smask = sidx + 64;                // 64
    float* pmax = (float*)(smask + 64);    // 8*128

    int g = blockIdx.x;
    int b = g >> 10;
    int t = threadIdx.x;

    for (int i = t; i < 4096; i += 128) sW1[i] = g_W1f[i];
    for (int i = t; i < 8192; i += 128) sW2[i] = g_W2f[i];
    if (t < 64) sB1[t] = g_b1f[t];
    if (t < 128) sB2[t] = g_b2f[t];
    if (t < 64) {
        int idx = g_knn_idx[g * Kf + t];
        float d = g_knn_dist[g * Kf + t];
        const float* p = &pos[(b * Nf + idx) * 3];
        float ccx = sampled[g * 3], ccy = sampled[g * 3 + 1], ccz = sampled[g * 3 + 2];
        sdpx[t] = p[0] - ccx;
        sdpy[t] = p[1] - ccy;
        sdpz[t] = p[2] - ccz;
        sidx[t] = idx;
        smask[t] = (d <= 0.2f) ? 1 : 0;
    }
    __syncthreads();

    // layer 1 (input 67 -> 64): A already holds x-part + bias; add dp part.
    {
        int c = t & 63;
        float w0 = g_W0f[c], w1 = g_W0f[64 + c], w2 = g_W0f[128 + c];
        for (int e = t; e < 4096; e += 128) {
            int k = e >> 6;
            float a = g_A[(b * Nf + sidx[k]) * 64 + c];
            float z = fmaf(sdpx[k], w0, a);
            z = fmaf(sdpy[k], w1, z);
            z = fmaf(sdpz[k], w2, z);
            act1[c * AKS + k] = fmaxf(z, 0.0f);
        }
    }
    __syncthreads();

    // layer 2 (64 -> 64): thread tile 8k x 4c, packed fp32x2 over k-pairs
    {
        int kg = t & 7, cg = t >> 3;  // cg 0..15
        int k0 = kg * 8, cc0 = cg * 4;
        unsigned long long acc[4][4];
#pragma unroll
        for (int a = 0; a < 4; a++)
#pragma unroll
            for (int bq = 0; bq < 4; bq++) acc[a][bq] = 0ull;
        for (int ci = 0; ci < 64; ci++) {
            const unsigned long long* ar = (const unsigned long long*)&act1[ci * AKS + k0];
            unsigned long long a0 = ar[0], a1 = ar[1], a2 = ar[2], a3 = ar[3];
            float4 w = *(const float4*)&sW1[ci * 64 + cc0];
            unsigned long long w0 = dup2(w.x), w1 = dup2(w.y), w2 = dup2(w.z), w3 = dup2(w.w);
            ffma2(acc[0][0], a0, w0); ffma2(acc[1][0], a1, w0);
            ffma2(acc[2][0], a2, w0); ffma2(acc[3][0], a3, w0);
            ffma2(acc[0][1], a0, w1); ffma2(acc[1][1], a1, w1);
            ffma2(acc[2][1], a2, w1); ffma2(acc[3][1], a3, w1);
            ffma2(acc[0][2], a0, w2); ffma2(acc[1][2], a1, w2);
            ffma2(acc[2][2], a2, w2); ffma2(acc[3][2], a3, w2);
            ffma2(acc[0][3], a0, w3); ffma2(acc[1][3], a1, w3);
            ffma2(acc[2][3], a2, w3); ffma2(acc[3][3], a3, w3);
        }
#pragma unroll
        for (int ccq = 0; ccq < 4; ccq++) {
            float bb = sB1[cc0 + ccq];
#pragma unroll
            for (int kp = 0; kp < 4; kp++) {
                float2 v = unpack2(acc[kp][ccq]);
                float2 r;
                r.x = fmaxf(v.x + bb, 0.0f);
                r.y = fmaxf(v.y + bb, 0.0f);
                *(float2*)&act2[(cc0 + ccq) * AKS + k0 + 2 * kp] = r;
            }
        }
    }
    __syncthreads();

    // layer 3 (64 -> 128) + masked max pool: thread tile 8k x 8c, packed fp32x2
    {
        int kg = t & 7, cg = t >> 3;  // cg 0..15 -> c0 0..120
        int k0 = kg * 8, cc0 = cg * 8;
        unsigned long long acc[4][8];
#pragma unroll
        for (int a = 0; a < 4; a++)
#pragma unroll
            for (int bq = 0; bq < 8; bq++) acc[a][bq] = 0ull;
        for (int ci = 0; ci < 64; ci++) {
            const unsigned long long* ar = (const unsigned long long*)&act2[ci * AKS + k0];
            unsigned long long a0 = ar[0], a1 = ar[1], a2 = ar[2], a3 = ar[3];
            float4 wA = *(const float4*)&sW2[ci * 128 + cc0];
            float4 wB = *(const float4*)&sW2[ci * 128 + cc0 + 4];
            unsigned long long w0 = dup2(wA.x), w1 = dup2(wA.y), w2 = dup2(wA.z), w3 = dup2(wA.w);
            unsigned long long w4 = dup2(wB.x), w5 = dup2(wB.y), w6 = dup2(wB.z), w7 = dup2(wB.w);
            ffma2(acc[0][0], a0, w0); ffma2(acc[1][0], a1, w0);
            ffma2(acc[2][0], a2, w0); ffma2(acc[3][0], a3, w0);
            ffma2(acc[0][1], a0, w1); ffma2(acc[1][1], a1, w1);
            ffma2(acc[2][1], a2, w1); ffma2(acc[3][1], a3, w1);
            ffma2(acc[0][2], a0, w2); ffma2(acc[1][2], a1, w2);
            ffma2(acc[2][2], a2, w2); ffma2(acc[3][2], a3, w2);
            ffma2(acc[0][3], a0, w3); ffma2(acc[1][3], a1, w3);
            ffma2(acc[2][3], a2, w3); ffma2(acc[3][3], a3, w3);
            ffma2(acc[0][4], a0, w4); ffma2(acc[1][4], a1, w4);
            ffma2(acc[2][4], a2, w4); ffma2(acc[3][4], a3, w4);
            ffma2(acc[0][5], a0, w5); ffma2(acc[1][5], a1, w5);
            ffma2(acc[2][5], a2, w5); ffma2(acc[3][5], a3, w5);
            ffma2(acc[0][6], a0, w6); ffma2(acc[1][6], a1, w6);
            ffma2(acc[2][6], a2, w6); ffma2(acc[3][6], a3, w6);
            ffma2(acc[0][7], a0, w7); ffma2(acc[1][7], a1, w7);
            ffma2(acc[2][7], a2, w7); ffma2(acc[3][7], a3, w7);
        }
#pragma unroll
        for (int ccq = 0; ccq < 8; ccq++) {
            float bb = sB2[cc0 + ccq];
            float m = -1e8f;
#pragma unroll
            for (int kp = 0; kp < 4; kp++) {
                float2 v = unpack2(acc[kp][ccq]);
                float h0 = fmaxf(v.x + bb, 0.0f);
                float h1 = fmaxf(v.y + bb, 0.0f);
                float q0 = smask[k0 + 2 * kp] ? h0 : -1e8f;
                float q1 = smask[k0 + 2 * kp + 1] ? h1 : -1e8f;
                m = fmaxf(m, fmaxf(q0, q1));
            }
            pmax[kg * 128 + cc0 + ccq] = m;
        }
    }
    __syncthreads();
    if (t < 128) {
        float m = pmax[t];
#pragma unroll
        for (int q = 1; q < 8; q++) m = fmaxf(m, pmax[q * 128 + t]);
        out[g * 128 + t] = m;
    }
}

// ---------------- launch ----------------
extern "C" void kernel_launch(void* const* d_in, const int* in_sizes, int n_in,
                              void* d_out, int out_size) {
    (void)in_sizes; (void)n_in; (void)out_size;
    const float* x = (const float*)d_in[0];
    const float* pos = (const float*)d_in[1];
    const float* W0 = (const float*)d_in[2];
    const float* b0 = (const float*)d_in[3];
    const float* gg0 = (const float*)d_in[4];
    const float* be0 = (const float*)d_in[5];
    const float* rm0 = (const float*)d_in[6];
    const float* rv0 = (const float*)d_in[7];
    const float* W1 = (const float*)d_in[8];
    const float* b1 = (const float*)d_in[9];
    const float* gg1 = (const float*)d_in[10];
    const float* be1 = (const float*)d_in[11];
    const float* rm1 = (const float*)d_in[12];
    const float* rv1 = (const float*)d_in[13];
    const float* W2 = (const float*)d_in[14];
    const float* b2 = (const float*)d_in[15];
    const float* gg2 = (const float*)d_in[16];
    const float* be2 = (const float*)d_in[17];
    const float* rm2 = (const float*)d_in[18];
    const float* rv2 = (const float*)d_in[19];

    float* out = (float*)d_out;
    float* sampled = out + (size_t)BZf * NSf * 128;

    const int knn_smem = 4096 * 4 + 4096 * 8 + 32;  // 49184
    const int mlp_smem = (64 * AKS * 2 + 4096 + 8192 + 64 + 128 + 64 * 5 + 1024) * 4;
    const int fps_smem = (Nf * 3 + 64 + 4) * 4;     // ~49.4KB
    cudaFuncSetAttribute(knn_kernel, cudaFuncAttributeMaxDynamicSharedMemorySize, knn_smem);
    cudaFuncSetAttribute(mlp_kernel, cudaFuncAttributeMaxDynamicSharedMemorySize, mlp_smem);
    cudaFuncSetAttribute(fps_kernel, cudaFuncAttributeMaxDynamicSharedMemorySize, fps_smem);

    fold_kernel<<<32, 256>>>(W0, b0, gg0, be0, rm0, rv0,
                             W1, b1, gg1, be1, rm1, rv1,
                             W2, b2, gg2, be2, rm2, rv2);
    pp_kernel<<<(BZf * Nf + 255) / 256, 256>>>(pos);
    fps_kernel<<<BZf, 1024, fps_smem>>>(pos, sampled);
    precA_kernel<<<BZf * Nf / 4, 64>>>(x);
    knn_kernel<<<BZf * NSf, 128, knn_smem>>>(pos, sampled);
    mlp_kernel<<<BZf * NSf, 128, mlp_smem>>>(pos, sampled, out);
}

// round 3
// speedup vs baseline: 1.5227x; 1.1606x over previous
#include <cuda_runtime.h>
#include <cstdint>

#define BZf 8
#define Nf 4096
#define CFf 64
#define NSf 1024
#define Kf 64

// ---------------- scratch (device globals; no allocation) ----------------
__device__ float g_W0f[67 * 64];
__device__ float g_b0f[64];
__device__ float g_W1f[64 * 64];
__device__ float g_b1f[64];
__device__ float g_W2f[64 * 128];
__device__ float g_b2f[128];
__device__ float g_pp[BZf * Nf];
__device__ float g_A[BZf * Nf * 64];          // 8 MB: per-point x·W0'[3:] + b0'
__device__ int   g_knn_idx[BZf * NSf * Kf];   // 2 MB
__device__ float g_knn_dist[BZf * NSf * Kf];  // 2 MB

// ---------------- packed fp32x2 helpers (sm_103a FFMA2) ----------------
__device__ __forceinline__ void ffma2(unsigned long long& acc, unsigned long long a,
                                      unsigned long long b) {
    asm("fma.rn.f32x2 %0, %1, %2, %0;" : "+l"(acc) : "l"(a), "l"(b));
}
__device__ __forceinline__ unsigned long long dup2(float v) {
    unsigned long long r;
    unsigned int u = __float_as_uint(v);
    asm("mov.b64 %0, {%1, %1};" : "=l"(r) : "r"(u));
    return r;
}
__device__ __forceinline__ float2 unpack2(unsigned long long v) {
    float2 f;
    asm("mov.b64 {%0, %1}, %2;" : "=f"(f.x), "=f"(f.y) : "l"(v));
    return f;
}

// ---------------- fold BN into weights ----------------
__global__ void fold_kernel(const float* W0, const float* b0, const float* gg0, const float* be0,
                            const float* rm0, const float* rv0,
                            const float* W1, const float* b1, const float* gg1, const float* be1,
                            const float* rm1, const float* rv1,
                            const float* W2, const float* b2, const float* gg2, const float* be2,
                            const float* rm2, const float* rv2) {
    int t = blockIdx.x * blockDim.x + threadIdx.x;
    int stride = gridDim.x * blockDim.x;
    for (int i = t; i < 67 * 64; i += stride) {
        int c = i & 63;
        float s = gg0[c] / sqrtf(rv0[c] + 1e-5f);
        g_W0f[i] = W0[i] * s;
    }
    for (int c = t; c < 64; c += stride) {
        float s = gg0[c] / sqrtf(rv0[c] + 1e-5f);
        g_b0f[c] = (b0[c] - rm0[c]) * s + be0[c];
    }
    for (int i = t; i < 64 * 64; i += stride) {
        int c = i & 63;
        float s = gg1[c] / sqrtf(rv1[c] + 1e-5f);
        g_W1f[i] = W1[i] * s;
    }
    for (int c = t; c < 64; c += stride) {
        float s = gg1[c] / sqrtf(rv1[c] + 1e-5f);
        g_b1f[c] = (b1[c] - rm1[c]) * s + be1[c];
    }
    for (int i = t; i < 64 * 128; i += stride) {
        int c = i & 127;
        float s = gg2[c] / sqrtf(rv2[c] + 1e-5f);
        g_W2f[i] = W2[i] * s;
    }
    for (int c = t; c < 128; c += stride) {
        float s = gg2[c] / sqrtf(rv2[c] + 1e-5f);
        g_b2f[c] = (b2[c] - rm2[c]) * s + be2[c];
    }
}

// ---------------- per-point squared norms (exact order: (x2+y2)+z2) ----------------
__global__ void pp_kernel(const float* pos) {
    int i = blockIdx.x * blockDim.x + threadIdx.x;
    if (i >= BZf * Nf) return;
    float x = pos[i * 3], y = pos[i * 3 + 1], z = pos[i * 3 + 2];
    g_pp[i] = __fadd_rn(__fadd_rn(__fmul_rn(x, x), __fmul_rn(y, y)), __fmul_rn(z, z));
}

// ---------------- FPS: single-sync double-buffered REDUX argmax (exact ties) ----------
__global__ __launch_bounds__(1024) void fps_kernel(const float* pos, float* sampled) {
    extern __shared__ unsigned char fsm[];
    float* spx = (float*)fsm;                           // 4096
    float* spy = spx + Nf;                              // 4096
    float* spz = spy + Nf;                              // 4096
    unsigned long long* red = (unsigned long long*)(spz + Nf);  // 2*32

    int b = blockIdx.x;
    int t = threadIdx.x;
    int lane = t & 31;
    int w = t >> 5;
    float px[4], py[4], pz[4], dist[4];
#pragma unroll
    for (int r = 0; r < 4; r++) {
        int i = t + (r << 10);
        const float* p = &pos[(b * Nf + i) * 3];
        float X = p[0], Y = p[1], Z = p[2];
        px[r] = X; py[r] = Y; pz[r] = Z;
        spx[i] = X; spy[i] = Y; spz[i] = Z;
        dist[r] = 1e10f;
    }
    if (t == 0) {
        const float* p = &pos[b * Nf * 3];
        float* o = &sampled[b * NSf * 3];
        o[0] = p[0]; o[1] = p[1]; o[2] = p[2];
    }
    __syncthreads();
    float cx = spx[0], cy = spy[0], cz = spz[0];
    int parity = 0;

    for (int s = 0; s < NSf - 1; s++) {
        unsigned int m;
        int bi;
        {
            float dx = __fsub_rn(px[0], cx);
            float dy = __fsub_rn(py[0], cy);
            float dz = __fsub_rn(pz[0], cz);
            float d = __fadd_rn(__fadd_rn(__fmul_rn(dx, dx), __fmul_rn(dy, dy)), __fmul_rn(dz, dz));
            dist[0] = fminf(dist[0], d);
            m = __float_as_uint(dist[0]);
            bi = t;
        }
#pragma unroll
        for (int r = 1; r < 4; r++) {
            float dx = __fsub_rn(px[r], cx);
            float dy = __fsub_rn(py[r], cy);
            float dz = __fsub_rn(pz[r], cz);
            float d = __fadd_rn(__fadd_rn(__fmul_rn(dx, dx), __fmul_rn(dy, dy)), __fmul_rn(dz, dz));
            dist[r] = fminf(dist[r], d);
            unsigned int bits = __float_as_uint(dist[r]);
            if (bits > m) { m = bits; bi = t + (r << 10); }
        }
        unsigned int wm = __reduce_max_sync(0xffffffffu, m);
        unsigned int cand = (m == wm) ? ~(unsigned int)bi : 0u;
        unsigned int wi = __reduce_max_sync(0xffffffffu, cand);
        if (lane == 0)
            red[parity * 32 + w] = ((unsigned long long)wm << 32) | (unsigned long long)wi;
        __syncthreads();
        // every warp redundantly does the final 32-wide reduce (no 2nd barrier)
        unsigned long long v = red[parity * 32 + lane];
        unsigned int d2 = (unsigned int)(v >> 32);
        unsigned int i2 = (unsigned int)v;
        unsigned int hi = __reduce_max_sync(0xffffffffu, d2);
        unsigned int c2 = (d2 == hi) ? i2 : 0u;
        unsigned int gi = __reduce_max_sync(0xffffffffu, c2);
        int nidx = (int)(~gi);
        cx = spx[nidx]; cy = spy[nidx]; cz = spz[nidx];
        if (t == 0) {
            float* o = &sampled[(b * NSf + s + 1) * 3];
            o[0] = cx; o[1] = cy; o[2] = cz;
        }
        parity ^= 1;
    }
}

// ---------------- precompute A = x . W0'[3:67] + b0' ----------------
__global__ __launch_bounds__(64) void precA_kernel(const float* x) {
    int row0 = blockIdx.x * 4;
    int c = threadIdx.x;
    __shared__ float sx[4][64];
#pragma unroll
    for (int r = 0; r < 4; r++) sx[r][c] = x[(row0 + r) * 64 + c];
    __syncthreads();
    float bv = g_b0f[c];
    float a0 = bv, a1 = bv, a2 = bv, a3 = bv;
#pragma unroll 8
    for (int i = 0; i < 64; i++) {
        float w = g_W0f[(3 + i) * 64 + c];
        a0 = fmaf(sx[0][i], w, a0);
        a1 = fmaf(sx[1][i], w, a1);
        a2 = fmaf(sx[2][i], w, a2);
        a3 = fmaf(sx[3][i], w, a3);
    }
    g_A[(row0 + 0) * 64 + c] = a0;
    g_A[(row0 + 1) * 64 + c] = a1;
    g_A[(row0 + 2) * 64 + c] = a2;
    g_A[(row0 + 3) * 64 + c] = a3;
}

// ---------------- kNN top-64 per centroid (exact top_k tie semantics) ----------------
#define KNT 256
__global__ __launch_bounds__(KNT) void knn_kernel(const float* pos, const float* sampled) {
    extern __shared__ unsigned char smem[];
    float* sd = (float*)smem;                                               // 4096 f
    unsigned long long* cand = (unsigned long long*)(smem + 4096 * 4);      // 4096 u64
    int* scnt = (int*)(smem + 4096 * 4 + 4096 * 8);                         // 6 ints
    __shared__ float cxs, cys, czs, sss;
    int g = blockIdx.x;
    int b = g >> 10;
    int t = threadIdx.x;
    if (t == 0) {
        float cx = sampled[g * 3], cy = sampled[g * 3 + 1], cz = sampled[g * 3 + 2];
        cxs = cx; cys = cy; czs = cz;
        sss = __fadd_rn(__fadd_rn(__fmul_rn(cx, cx), __fmul_rn(cy, cy)), __fmul_rn(cz, cz));
    }
    if (t < 6) scnt[t] = 0;
    __syncthreads();
    float sx = cxs, sy = cys, sz = czs, ss = sss;
    const float T0 = 0.18f, T1 = 0.25f, T2 = 0.35f, T3 = 0.55f;
    int c0 = 0, c1 = 0, c2 = 0, c3 = 0;
    const float* pb = &pos[b * Nf * 3];
    const float* ppb = &g_pp[b * Nf];
    for (int p = t; p < Nf; p += KNT) {
        float X = pb[p * 3], Y = pb[p * 3 + 1], Z = pb[p * 3 + 2];
        float dot = __fadd_rn(__fadd_rn(__fmul_rn(sx, X), __fmul_rn(sy, Y)), __fmul_rn(sz, Z));
        float d2 = __fsub_rn(__fadd_rn(ss, ppb[p]), __fmul_rn(2.0f, dot));
        float d = sqrtf(fmaxf(d2, 0.0f));
        sd[p] = d;
        c0 += (d <= T0); c1 += (d <= T1); c2 += (d <= T2); c3 += (d <= T3);
    }
    atomicAdd(&scnt[0], c0);
    atomicAdd(&scnt[1], c1);
    atomicAdd(&scnt[2], c2);
    atomicAdd(&scnt[3], c3);
    __syncthreads();
    float thr;
    if (scnt[0] >= Kf) thr = T0;
    else if (scnt[1] >= Kf) thr = T1;
    else if (scnt[2] >= Kf) thr = T2;
    else if (scnt[3] >= Kf) thr = T3;
    else thr = 1e30f;
    for (int p = t; p < Nf; p += KNT) {
        float d = sd[p];
        if (d <= thr) {
            int slot = atomicAdd(&scnt[5], 1);
            cand[slot] = ((unsigned long long)__float_as_uint(d) << 32) | (unsigned int)p;
        }
    }
    __syncthreads();
    int cnt = scnt[5];
    int P = 128;
    while (P < cnt) P <<= 1;
    for (int i = t; i < P; i += KNT)
        if (i >= cnt) cand[i] = 0xffffffffffffffffull;
    __syncthreads();
    for (int k2 = 2; k2 <= P; k2 <<= 1) {
        for (int j = k2 >> 1; j > 0; j >>= 1) {
            for (int i = t; i < P; i += KNT) {
                int ij = i ^ j;
                if (ij > i) {
                    unsigned long long a = cand[i], bb = cand[ij];
                    bool up = ((i & k2) == 0);
                    if ((a > bb) == up) { cand[i] = bb; cand[ij] = a; }
                }
            }
            __syncthreads();
        }
    }
    if (t < Kf) {
        unsigned long long key = cand[t];
        g_knn_idx[g * Kf + t] = (int)(key & 0xffffffffull);
        g_knn_dist[g * Kf + t] = __uint_as_float((unsigned int)(key >> 32));
    }
}

// ---- fused MLP (FFMA2, conflict-free tiling: k warp-uniform, c per-lane) + maxpool ----
#define AKS 66  // activation row stride ([c][k] layout)
__global__ __launch_bounds__(128) void mlp_kernel(const float* pos, const float* sampled, float* out) {
    extern __shared__ unsigned char smem[];
    float* act1 = (float*)smem;            // 64*66
    float* act2 = act1 + 64 * AKS;         // 64*66
    float* sW1 = act2 + 64 * AKS;          // 4096
    float* sW2 = sW1 + 4096;               // 8192
    float* sB1 = sW2 + 8192;               // 64
    float* sB2 = sB1 + 64;                 // 128
    float* sdpx = sB2 + 128;               // 64
    float* sdpy = sdpx + 64;               // 64
    float* sdpz = sdpy + 64;               // 64
    int* sidx = (int*)(sdpz + 64);         // 64
    int* smask = sidx + 64;                // 64
    float* pmax = (float*)(smask + 64);    // 4*128

    int g = blockIdx.x;
    int b = g >> 10;
    int t = threadIdx.x;
    int w = t >> 5, lane = t & 31;

    for (int i = t; i < 4096; i += 128) sW1[i] = g_W1f[i];
    for (int i = t; i < 8192; i += 128) sW2[i] = g_W2f[i];
    if (t < 64) sB1[t] = g_b1f[t];
    if (t < 128) sB2[t] = g_b2f[t];
    if (t < 64) {
        int idx = g_knn_idx[g * Kf + t];
        float d = g_knn_dist[g * Kf + t];
        const float* p = &pos[(b * Nf + idx) * 3];
        float ccx = sampled[g * 3], ccy = sampled[g * 3 + 1], ccz = sampled[g * 3 + 2];
        sdpx[t] = p[0] - ccx;
        sdpy[t] = p[1] - ccy;
        sdpz[t] = p[2] - ccz;
        sidx[t] = idx;
        smask[t] = (d <= 0.2f) ? 1 : 0;
    }
    __syncthreads();

    // layer 1 (input 67 -> 64): A already holds x-part + bias; add dp part.
    {
        int c = t & 63;
        float w0 = g_W0f[c], w1 = g_W0f[64 + c], w2 = g_W0f[128 + c];
        for (int e = t; e < 4096; e += 128) {
            int k = e >> 6;
            float a = g_A[(b * Nf + sidx[k]) * 64 + c];
            float z = fmaf(sdpx[k], w0, a);
            z = fmaf(sdpy[k], w1, z);
            z = fmaf(sdpz[k], w2, z);
            act1[c * AKS + k] = fmaxf(z, 0.0f);
        }
    }
    __syncthreads();

    // layer 2 (64 -> 64): warp owns k0 = w*16 (act loads broadcast), lane owns 2 channels
    {
        int k0 = w * 16, cc0 = lane * 2;
        unsigned long long acc[8][2];
#pragma unroll
        for (int j = 0; j < 8; j++) { acc[j][0] = 0ull; acc[j][1] = 0ull; }
        for (int ci = 0; ci < 64; ci++) {
            const unsigned long long* ar = (const unsigned long long*)&act1[ci * AKS + k0];
            unsigned long long a[8];
#pragma unroll
            for (int j = 0; j < 8; j++) a[j] = ar[j];
            float2 wv = *(const float2*)&sW1[ci * 64 + cc0];
            unsigned long long w0 = dup2(wv.x), w1 = dup2(wv.y);
#pragma unroll
            for (int j = 0; j < 8; j++) {
                ffma2(acc[j][0], a[j], w0);
                ffma2(acc[j][1], a[j], w1);
            }
        }
#pragma unroll
        for (int ccq = 0; ccq < 2; ccq++) {
            float bb = sB1[cc0 + ccq];
#pragma unroll
            for (int kp = 0; kp < 8; kp++) {
                float2 v = unpack2(acc[kp][ccq]);
                float2 r;
                r.x = fmaxf(v.x + bb, 0.0f);
                r.y = fmaxf(v.y + bb, 0.0f);
                *(float2*)&act2[(cc0 + ccq) * AKS + k0 + 2 * kp] = r;
            }
        }
    }
    __syncthreads();

    // layer 3 (64 -> 128) + masked max pool: warp owns k0 = w*16, lane owns 4 channels
    {
        int k0 = w * 16, cc0 = lane * 4;
        unsigned long long acc[8][4];
#pragma unroll
        for (int j = 0; j < 8; j++)
#pragma unroll
            for (int q = 0; q < 4; q++) acc[j][q] = 0ull;
        for (int ci = 0; ci < 64; ci++) {
            const unsigned long long* ar = (const unsigned long long*)&act2[ci * AKS + k0];
            unsigned long long a[8];
#pragma unroll
            for (int j = 0; j < 8; j++) a[j] = ar[j];
            float4 wv = *(const float4*)&sW2[ci * 128 + cc0];
            unsigned long long w0 = dup2(wv.x), w1 = dup2(wv.y), w2 = dup2(wv.z), w3 = dup2(wv.w);
#pragma unroll
            for (int j = 0; j < 8; j++) {
                ffma2(acc[j][0], a[j], w0);
                ffma2(acc[j][1], a[j], w1);
                ffma2(acc[j][2], a[j], w2);
                ffma2(acc[j][3], a[j], w3);
            }
        }
#pragma unroll
        for (int ccq = 0; ccq < 4; ccq++) {
            float bb = sB2[cc0 + ccq];
            float m = -1e8f;
#pragma unroll
            for (int kp = 0; kp < 8; kp++) {
                float2 v = unpack2(acc[kp][ccq]);
                float h0 = fmaxf(v.x + bb, 0.0f);
                float h1 = fmaxf(v.y + bb, 0.0f);
                float q0 = smask[k0 + 2 * kp] ? h0 : -1e8f;
                float q1 = smask[k0 + 2 * kp + 1] ? h1 : -1e8f;
                m = fmaxf(m, fmaxf(q0, q1));
            }
            pmax[w * 128 + cc0 + ccq] = m;
        }
    }
    __syncthreads();
    if (t < 128) {
        float m = pmax[t];
#pragma unroll
        for (int q = 1; q < 4; q++) m = fmaxf(m, pmax[q * 128 + t]);
        out[g * 128 + t] = m;
    }
}

// ---------------- launch ----------------
extern "C" void kernel_launch(void* const* d_in, const int* in_sizes, int n_in,
                              void* d_out, int out_size) {
    (void)in_sizes; (void)n_in; (void)out_size;
    const float* x = (const float*)d_in[0];
    const float* pos = (const float*)d_in[1];
    const float* W0 = (const float*)d_in[2];
    const float* b0 = (const float*)d_in[3];
    const float* gg0 = (const float*)d_in[4];
    const float* be0 = (const float*)d_in[5];
    const float* rm0 = (const float*)d_in[6];
    const float* rv0 = (const float*)d_in[7];
    const float* W1 = (const float*)d_in[8];
    const float* b1 = (const float*)d_in[9];
    const float* gg1 = (const float*)d_in[10];
    const float* be1 = (const float*)d_in[11];
    const float* rm1 = (const float*)d_in[12];
    const float* rv1 = (const float*)d_in[13];
    const float* W2 = (const float*)d_in[14];
    const float* b2 = (const float*)d_in[15];
    const float* gg2 = (const float*)d_in[16];
    const float* be2 = (const float*)d_in[17];
    const float* rm2 = (const float*)d_in[18];
    const float* rv2 = (const float*)d_in[19];

    float* out = (float*)d_out;
    float* sampled = out + (size_t)BZf * NSf * 128;

    const int knn_smem = 4096 * 4 + 4096 * 8 + 32;  // 49184
    const int mlp_smem = (64 * AKS * 2 + 4096 + 8192 + 64 + 128 + 64 * 5 + 512) * 4;
    const int fps_smem = Nf * 3 * 4 + 2 * 32 * 8;   // 49664
    cudaFuncSetAttribute(knn_kernel, cudaFuncAttributeMaxDynamicSharedMemorySize, knn_smem);
    cudaFuncSetAttribute(mlp_kernel, cudaFuncAttributeMaxDynamicSharedMemorySize, mlp_smem);
    cudaFuncSetAttribute(fps_kernel, cudaFuncAttributeMaxDynamicSharedMemorySize, fps_smem);

    fold_kernel<<<32, 256>>>(W0, b0, gg0, be0, rm0, rv0,
                             W1, b1, gg1, be1, rm1, rv1,
                             W2, b2, gg2, be2, rm2, rv2);
    pp_kernel<<<(BZf * Nf + 255) / 256, 256>>>(pos);
    fps_kernel<<<BZf, 1024, fps_smem>>>(pos, sampled);
    precA_kernel<<<BZf * Nf / 4, 64>>>(x);
    knn_kernel<<<BZf * NSf, KNT, knn_smem>>>(pos, sampled);
    mlp_kernel<<<BZf * NSf, 128, mlp_smem>>>(pos, sampled, out);
}

// round 4
// speedup vs baseline: 1.5576x; 1.0229x over previous
#include <cuda_runtime.h>
#include <cstdint>

#define BZf 8
#define Nf 4096
#define CFf 64
#define NSf 1024
#define Kf 64

typedef unsigned long long u64;

// ---------------- scratch (device globals; no allocation) ----------------
__device__ float g_W0f[67 * 64];
__device__ float g_b0f[64];
__device__ float g_W1f[64 * 64];
__device__ float g_b1f[64];
__device__ float g_W2f[64 * 128];
__device__ float g_b2f[128];
__device__ float g_pp[BZf * Nf];
__device__ float g_A[BZf * Nf * 64];          // 8 MB: per-point x·W0'[3:] + b0'
__device__ int   g_knn_idx[BZf * NSf * Kf];   // 2 MB
__device__ float g_knn_dist[BZf * NSf * Kf];  // 2 MB

// ---------------- packed fp32x2 helpers (sm_103a) ----------------
__device__ __forceinline__ void ffma2(u64& acc, u64 a, u64 b) {
    asm("fma.rn.f32x2 %0, %1, %2, %0;" : "+l"(acc) : "l"(a), "l"(b));
}
__device__ __forceinline__ u64 add2(u64 a, u64 b) {
    u64 r;
    asm("add.rn.f32x2 %0, %1, %2;" : "=l"(r) : "l"(a), "l"(b));
    return r;
}
__device__ __forceinline__ u64 mul2(u64 a, u64 b) {
    u64 r;
    asm("mul.rn.f32x2 %0, %1, %2;" : "=l"(r) : "l"(a), "l"(b));
    return r;
}
__device__ __forceinline__ u64 dup2(float v) {
    u64 r;
    unsigned int u = __float_as_uint(v);
    asm("mov.b64 %0, {%1, %1};" : "=l"(r) : "r"(u));
    return r;
}
__device__ __forceinline__ u64 pack2(float lo, float hi) {
    u64 r;
    asm("mov.b64 %0, {%1, %2};" : "=l"(r) : "f"(lo), "f"(hi));
    return r;
}
__device__ __forceinline__ float2 unpack2(u64 v) {
    float2 f;
    asm("mov.b64 {%0, %1}, %2;" : "=f"(f.x), "=f"(f.y) : "l"(v));
    return f;
}

// ---------------- prep: fold BN into weights + per-point squared norms ----------------
__global__ void prep_kernel(const float* pos,
                            const float* W0, const float* b0, const float* gg0, const float* be0,
                            const float* rm0, const float* rv0,
                            const float* W1, const float* b1, const float* gg1, const float* be1,
                            const float* rm1, const float* rv1,
                            const float* W2, const float* b2, const float* gg2, const float* be2,
                            const float* rm2, const float* rv2) {
    int t = blockIdx.x * blockDim.x + threadIdx.x;
    int stride = gridDim.x * blockDim.x;
    for (int i = t; i < 67 * 64; i += stride) {
        int c = i & 63;
        float s = gg0[c] / sqrtf(rv0[c] + 1e-5f);
        g_W0f[i] = W0[i] * s;
    }
    for (int c = t; c < 64; c += stride) {
        float s = gg0[c] / sqrtf(rv0[c] + 1e-5f);
        g_b0f[c] = (b0[c] - rm0[c]) * s + be0[c];
    }
    for (int i = t; i < 64 * 64; i += stride) {
        int c = i & 63;
        float s = gg1[c] / sqrtf(rv1[c] + 1e-5f);
        g_W1f[i] = W1[i] * s;
    }
    for (int c = t; c < 64; c += stride) {
        float s = gg1[c] / sqrtf(rv1[c] + 1e-5f);
        g_b1f[c] = (b1[c] - rm1[c]) * s + be1[c];
    }
    for (int i = t; i < 64 * 128; i += stride) {
        int c = i & 127;
        float s = gg2[c] / sqrtf(rv2[c] + 1e-5f);
        g_W2f[i] = W2[i] * s;
    }
    for (int c = t; c < 128; c += stride) {
        float s = gg2[c] / sqrtf(rv2[c] + 1e-5f);
        g_b2f[c] = (b2[c] - rm2[c]) * s + be2[c];
    }
    for (int i = t; i < BZf * Nf; i += stride) {
        float x = pos[i * 3], y = pos[i * 3 + 1], z = pos[i * 3 + 2];
        g_pp[i] = __fadd_rn(__fadd_rn(__fmul_rn(x, x), __fmul_rn(y, y)), __fmul_rn(z, z));
    }
}

// ---------------- FPS: packed f32x2 distances + REDUX argmax (exact ties) ----------
__global__ __launch_bounds__(1024) void fps_kernel(const float* pos, float* sampled) {
    extern __shared__ unsigned char fsm[];
    float* spx = (float*)fsm;                 // 4096
    float* spy = spx + Nf;                    // 4096
    float* spz = spy + Nf;                    // 4096
    u64* red = (u64*)(spz + Nf);              // 2*32

    int b = blockIdx.x;
    int t = threadIdx.x;
    int lane = t & 31;
    int w = t >> 5;
    float dist[4];
    u64 pxp[2], pyp[2], pzp[2];
    {
        float px[4], py[4], pz[4];
#pragma unroll
        for (int r = 0; r < 4; r++) {
            int i = t + (r << 10);
            const float* p = &pos[(b * Nf + i) * 3];
            float X = p[0], Y = p[1], Z = p[2];
            px[r] = X; py[r] = Y; pz[r] = Z;
            spx[i] = X; spy[i] = Y; spz[i] = Z;
            dist[r] = 1e10f;
        }
        pxp[0] = pack2(px[0], px[1]); pxp[1] = pack2(px[2], px[3]);
        pyp[0] = pack2(py[0], py[1]); pyp[1] = pack2(py[2], py[3]);
        pzp[0] = pack2(pz[0], pz[1]); pzp[1] = pack2(pz[2], pz[3]);
    }
    if (t == 0) {
        const float* p = &pos[b * Nf * 3];
        float* o = &sampled[b * NSf * 3];
        o[0] = p[0]; o[1] = p[1]; o[2] = p[2];
    }
    __syncthreads();
    float cx = spx[0], cy = spy[0], cz = spz[0];
    int parity = 0;

    for (int s = 0; s < NSf - 1; s++) {
        u64 ncx = dup2(-cx), ncy = dup2(-cy), ncz = dup2(-cz);
#pragma unroll
        for (int p = 0; p < 2; p++) {
            u64 dx = add2(pxp[p], ncx);
            u64 dy = add2(pyp[p], ncy);
            u64 dz = add2(pzp[p], ncz);
            u64 xx = mul2(dx, dx);
            u64 yy = mul2(dy, dy);
            u64 zz = mul2(dz, dz);
            u64 dd = add2(add2(xx, yy), zz);
            float2 f = unpack2(dd);
            dist[2 * p] = fminf(dist[2 * p], f.x);
            dist[2 * p + 1] = fminf(dist[2 * p + 1], f.y);
        }
        float m = fmaxf(fmaxf(dist[0], dist[1]), fmaxf(dist[2], dist[3]));
        unsigned int mb = __float_as_uint(m);
        unsigned int wm = __reduce_max_sync(0xffffffffu, mb);
        // first-match (lowest r) within the thread, ~idx-max across lanes -> global min idx
        unsigned int cand = 0u;
        if (__float_as_uint(dist[3]) == wm) cand = ~(unsigned int)(t + 3072);
        if (__float_as_uint(dist[2]) == wm) cand = ~(unsigned int)(t + 2048);
        if (__float_as_uint(dist[1]) == wm) cand = ~(unsigned int)(t + 1024);
        if (__float_as_uint(dist[0]) == wm) cand = ~(unsigned int)t;
        unsigned int wi = __reduce_max_sync(0xffffffffu, cand);
        if (lane == 0)
            red[parity * 32 + w] = ((u64)wm << 32) | (u64)wi;
        __syncthreads();
        u64 v = red[parity * 32 + lane];
        unsigned int d2 = (unsigned int)(v >> 32);
        unsigned int i2 = (unsigned int)v;
        unsigned int hi = __reduce_max_sync(0xffffffffu, d2);
        unsigned int c2 = (d2 == hi) ? i2 : 0u;
        unsigned int gi = __reduce_max_sync(0xffffffffu, c2);
        int nidx = (int)(~gi);
        cx = spx[nidx]; cy = spy[nidx]; cz = spz[nidx];
        if (t == 0) {
            float* o = &sampled[(b * NSf + s + 1) * 3];
            o[0] = cx; o[1] = cy; o[2] = cz;
        }
        parity ^= 1;
    }
}

// ---------------- merged precA + kNN (branch by block range) ----------------
#define PKA 2048  // precA blocks (16 rows each)
__global__ __launch_bounds__(256) void pk_kernel(const float* x, const float* pos,
                                                 const float* sampled) {
    extern __shared__ unsigned char smem[];
    int t = threadIdx.x;
    if (blockIdx.x < PKA) {
        // ---- precA: A = x . W0'[3:67] + b0', 16 rows per block ----
        float* sx = (float*)smem;  // 16*64
        int base = blockIdx.x * 16;
        for (int i = t; i < 16 * 64; i += 256) sx[i] = x[base * 64 + i];
        __syncthreads();
        int c = t & 63, rg = t >> 6;  // 4 row-groups x 4 rows
        float bv = g_b0f[c];
        float a0 = bv, a1 = bv, a2 = bv, a3 = bv;
        const float* sxr = &sx[rg * 4 * 64];
#pragma unroll 8
        for (int i = 0; i < 64; i++) {
            float wv = g_W0f[(3 + i) * 64 + c];
            a0 = fmaf(sxr[i], wv, a0);
            a1 = fmaf(sxr[64 + i], wv, a1);
            a2 = fmaf(sxr[128 + i], wv, a2);
            a3 = fmaf(sxr[192 + i], wv, a3);
        }
        int r0 = base + rg * 4;
        g_A[(r0 + 0) * 64 + c] = a0;
        g_A[(r0 + 1) * 64 + c] = a1;
        g_A[(r0 + 2) * 64 + c] = a2;
        g_A[(r0 + 3) * 64 + c] = a3;
        return;
    }
    // ---- kNN top-64 per centroid (exact top_k tie semantics) ----
    float* sd = (float*)smem;                                   // 4096 f
    u64* cand = (u64*)(smem + 4096 * 4);                        // 4096 u64
    int* scnt = (int*)(smem + 4096 * 4 + 4096 * 8);             // 6 ints
    __shared__ float cxs, cys, czs, sss;
    int g = blockIdx.x - PKA;
    int b = g >> 10;
    if (t == 0) {
        float cx = sampled[g * 3], cy = sampled[g * 3 + 1], cz = sampled[g * 3 + 2];
        cxs = cx; cys = cy; czs = cz;
        sss = __fadd_rn(__fadd_rn(__fmul_rn(cx, cx), __fmul_rn(cy, cy)), __fmul_rn(cz, cz));
    }
    if (t < 6) scnt[t] = 0;
    __syncthreads();
    float sx = cxs, sy = cys, sz = czs, ss = sss;
    const float T0 = 0.18f, T1 = 0.25f, T2 = 0.35f, T3 = 0.55f;
    int c0 = 0, c1 = 0, c2 = 0, c3 = 0;
    const float* pb = &pos[b * Nf * 3];
    const float* ppb = &g_pp[b * Nf];
    for (int p = t; p < Nf; p += 256) {
        float X = pb[p * 3], Y = pb[p * 3 + 1], Z = pb[p * 3 + 2];
        float dot = __fadd_rn(__fadd_rn(__fmul_rn(sx, X), __fmul_rn(sy, Y)), __fmul_rn(sz, Z));
        float d2 = __fsub_rn(__fadd_rn(ss, ppb[p]), __fmul_rn(2.0f, dot));
        float d = sqrtf(fmaxf(d2, 0.0f));
        sd[p] = d;
        c0 += (d <= T0); c1 += (d <= T1); c2 += (d <= T2); c3 += (d <= T3);
    }
    atomicAdd(&scnt[0], c0);
    atomicAdd(&scnt[1], c1);
    atomicAdd(&scnt[2], c2);
    atomicAdd(&scnt[3], c3);
    __syncthreads();
    float thr;
    if (scnt[0] >= Kf) thr = T0;
    else if (scnt[1] >= Kf) thr = T1;
    else if (scnt[2] >= Kf) thr = T2;
    else if (scnt[3] >= Kf) thr = T3;
    else thr = 1e30f;
    for (int p = t; p < Nf; p += 256) {
        float d = sd[p];
        if (d <= thr) {
            int slot = atomicAdd(&scnt[5], 1);
            cand[slot] = ((u64)__float_as_uint(d) << 32) | (unsigned int)p;
        }
    }
    __syncthreads();
    int cnt = scnt[5];
    int P = 128;
    while (P < cnt) P <<= 1;
    for (int i = t; i < P; i += 256)
        if (i >= cnt) cand[i] = 0xffffffffffffffffull;
    __syncthreads();
    for (int k2 = 2; k2 <= P; k2 <<= 1) {
        for (int j = k2 >> 1; j > 0; j >>= 1) {
            for (int i = t; i < P; i += 256) {
                int ij = i ^ j;
                if (ij > i) {
                    u64 a = cand[i], bb = cand[ij];
                    bool up = ((i & k2) == 0);
                    if ((a > bb) == up) { cand[i] = bb; cand[ij] = a; }
                }
            }
            __syncthreads();
        }
    }
    if (t < Kf) {
        u64 key = cand[t];
        g_knn_idx[g * Kf + t] = (int)(key & 0xffffffffull);
        g_knn_dist[g * Kf + t] = __uint_as_float((unsigned int)(key >> 32));
    }
}

// ---- fused MLP (FFMA2, low-LDS k8xc tiles) + masked max-pool per centroid ----
#define AKS 68  // activation row stride ([c][k] layout), 16B-aligned rows
__global__ __launch_bounds__(128) void mlp_kernel(const float* pos, const float* sampled, float* out) {
    extern __shared__ unsigned char smem[];
    float* act1 = (float*)smem;            // 64*68
    float* act2 = act1 + 64 * AKS;         // 64*68
    float* sW1 = act2 + 64 * AKS;          // 4096
    float* sW2 = sW1 + 4096;               // 8192
    float* sB1 = sW2 + 8192;               // 64
    float* sB2 = sB1 + 64;                 // 128
    float* sdpx = sB2 + 128;               // 64
    float* sdpy = sdpx + 64;               // 64
    float* sdpz = sdpy + 64;               // 64
    int* sidx = (int*)(sdpz + 64);         // 64
    int* smask = sidx + 64;                // 64
    float* pmax = (float*)(smask + 64);    // 8*128

    int g = blockIdx.x;
    int b = g >> 10;
    int t = threadIdx.x;
    int w = t >> 5, lane = t & 31;
    int ksub = lane >> 4;                  // 0/1
    int k0 = w * 16 + ksub * 8;            // this thread's 8 k's
    int cL = lane & 15;

    for (int i = t; i < 4096; i += 128) sW1[i] = g_W1f[i];
    for (int i = t; i < 8192; i += 128) sW2[i] = g_W2f[i];
    if (t < 64) sB1[t] = g_b1f[t];
    if (t < 128) sB2[t] = g_b2f[t];
    if (t < 64) {
        int idx = g_knn_idx[g * Kf + t];
        float d = g_knn_dist[g * Kf + t];
        const float* p = &pos[(b * Nf + idx) * 3];
        float ccx = sampled[g * 3], ccy = sampled[g * 3 + 1], ccz = sampled[g * 3 + 2];
        sdpx[t] = p[0] - ccx;
        sdpy[t] = p[1] - ccy;
        sdpz[t] = p[2] - ccz;
        sidx[t] = idx;
        smask[t] = (d <= 0.2f) ? 1 : 0;
    }
    __syncthreads();

    // layer 1 (input 67 -> 64): A already holds x-part + bias; add dp part.
    {
        int c = t & 63;
        float w0 = g_W0f[c], w1 = g_W0f[64 + c], w2 = g_W0f[128 + c];
        for (int e = t; e < 4096; e += 128) {
            int k = e >> 6;
            float a = g_A[(b * Nf + sidx[k]) * 64 + c];
            float z = fmaf(sdpx[k], w0, a);
            z = fmaf(sdpy[k], w1, z);
            z = fmaf(sdpz[k], w2, z);
            act1[c * AKS + k] = fmaxf(z, 0.0f);
        }
    }
    __syncthreads();

    // layer 2 (64 -> 64): thread tile 8k x 4c (4 a-loads + 1 w-load per ci)
    {
        int cc0 = cL * 4;
        u64 acc[4][4];
#pragma unroll
        for (int j = 0; j < 4; j++)
#pragma unroll
            for (int q = 0; q < 4; q++) acc[j][q] = 0ull;
        for (int ci = 0; ci < 64; ci++) {
            const u64* ar = (const u64*)&act1[ci * AKS + k0];
            u64 a0 = ar[0], a1 = ar[1], a2 = ar[2], a3 = ar[3];
            float4 wv = *(const float4*)&sW1[ci * 64 + cc0];
            u64 w0 = dup2(wv.x), w1 = dup2(wv.y), w2 = dup2(wv.z), w3 = dup2(wv.w);
            ffma2(acc[0][0], a0, w0); ffma2(acc[1][0], a1, w0);
            ffma2(acc[2][0], a2, w0); ffma2(acc[3][0], a3, w0);
            ffma2(acc[0][1], a0, w1); ffma2(acc[1][1], a1, w1);
            ffma2(acc[2][1], a2, w1); ffma2(acc[3][1], a3, w1);
            ffma2(acc[0][2], a0, w2); ffma2(acc[1][2], a1, w2);
            ffma2(acc[2][2], a2, w2); ffma2(acc[3][2], a3, w2);
            ffma2(acc[0][3], a0, w3); ffma2(acc[1][3], a1, w3);
            ffma2(acc[2][3], a2, w3); ffma2(acc[3][3], a3, w3);
        }
#pragma unroll
        for (int cq = 0; cq < 4; cq++) {
            float bb = sB1[cc0 + cq];
#pragma unroll
            for (int kp = 0; kp < 4; kp++) {
                float2 v = unpack2(acc[kp][cq]);
                float2 r;
                r.x = fmaxf(v.x + bb, 0.0f);
                r.y = fmaxf(v.y + bb, 0.0f);
                *(float2*)&act2[(cc0 + cq) * AKS + k0 + 2 * kp] = r;
            }
        }
    }
    __syncthreads();

    // layer 3 (64 -> 128) + masked max pool: thread tile 8k x 8c
    {
        int cc0 = cL * 8;
        u64 acc[4][8];
#pragma unroll
        for (int j = 0; j < 4; j++)
#pragma unroll
            for (int q = 0; q < 8; q++) acc[j][q] = 0ull;
        for (int ci = 0; ci < 64; ci++) {
            const u64* ar = (const u64*)&act2[ci * AKS + k0];
            u64 a0 = ar[0], a1 = ar[1], a2 = ar[2], a3 = ar[3];
            float4 wa = *(const float4*)&sW2[ci * 128 + cc0];
            float4 wb = *(const float4*)&sW2[ci * 128 + cc0 + 4];
            u64 w0 = dup2(wa.x), w1 = dup2(wa.y), w2 = dup2(wa.z), w3 = dup2(wa.w);
            u64 w4 = dup2(wb.x), w5 = dup2(wb.y), w6 = dup2(wb.z), w7 = dup2(wb.w);
            ffma2(acc[0][0], a0, w0); ffma2(acc[1][0], a1, w0);
            ffma2(acc[2][0], a2, w0); ffma2(acc[3][0], a3, w0);
            ffma2(acc[0][1], a0, w1); ffma2(acc[1][1], a1, w1);
            ffma2(acc[2][1], a2, w1); ffma2(acc[3][1], a3, w1);
            ffma2(acc[0][2], a0, w2); ffma2(acc[1][2], a1, w2);
            ffma2(acc[2][2], a2, w2); ffma2(acc[3][2], a3, w2);
            ffma2(acc[0][3], a0, w3); ffma2(acc[1][3], a1, w3);
            ffma2(acc[2][3], a2, w3); ffma2(acc[3][3], a3, w3);
            ffma2(acc[0][4], a0, w4); ffma2(acc[1][4], a1, w4);
            ffma2(acc[2][4], a2, w4); ffma2(acc[3][4], a3, w4);
            ffma2(acc[0][5], a0, w5); ffma2(acc[1][5], a1, w5);
            ffma2(acc[2][5], a2, w5); ffma2(acc[3][5], a3, w5);
            ffma2(acc[0][6], a0, w6); ffma2(acc[1][6], a1, w6);
            ffma2(acc[2][6], a2, w6); ffma2(acc[3][6], a3, w6);
            ffma2(acc[0][7], a0, w7); ffma2(acc[1][7], a1, w7);
            ffma2(acc[2][7], a2, w7); ffma2(acc[3][7], a3, w7);
        }
#pragma unroll
        for (int cq = 0; cq < 8; cq++) {
            float bb = sB2[cc0 + cq];
            float m = -1e8f;
#pragma unroll
            for (int kp = 0; kp < 4; kp++) {
                float2 v = unpack2(acc[kp][cq]);
                float h0 = fmaxf(v.x + bb, 0.0f);
                float h1 = fmaxf(v.y + bb, 0.0f);
                float q0 = smask[k0 + 2 * kp] ? h0 : -1e8f;
                float q1 = smask[k0 + 2 * kp + 1] ? h1 : -1e8f;
                m = fmaxf(m, fmaxf(q0, q1));
            }
            pmax[(w * 2 + ksub) * 128 + cc0 + cq] = m;
        }
    }
    __syncthreads();
    if (t < 128) {
        float m = pmax[t];
#pragma unroll
        for (int q = 1; q < 8; q++) m = fmaxf(m, pmax[q * 128 + t]);
        out[g * 128 + t] = m;
    }
}

// ---------------- launch ----------------
extern "C" void kernel_launch(void* const* d_in, const int* in_sizes, int n_in,
                              void* d_out, int out_size) {
    (void)in_sizes; (void)n_in; (void)out_size;
    const float* x = (const float*)d_in[0];
    const float* pos = (const float*)d_in[1];
    const float* W0 = (const float*)d_in[2];
    const float* b0 = (const float*)d_in[3];
    const float* gg0 = (const float*)d_in[4];
    const float* be0 = (const float*)d_in[5];
    const float* rm0 = (const float*)d_in[6];
    const float* rv0 = (const float*)d_in[7];
    const float* W1 = (const float*)d_in[8];
    const float* b1 = (const float*)d_in[9];
    const float* gg1 = (const float*)d_in[10];
    const float* be1 = (const float*)d_in[11];
    const float* rm1 = (const float*)d_in[12];
    const float* rv1 = (const float*)d_in[13];
    const float* W2 = (const float*)d_in[14];
    const float* b2 = (const float*)d_in[15];
    const float* gg2 = (const float*)d_in[16];
    const float* be2 = (const float*)d_in[17];
    const float* rm2 = (const float*)d_in[18];
    const float* rv2 = (const float*)d_in[19];

    float* out = (float*)d_out;
    float* sampled = out + (size_t)BZf * NSf * 128;

    const int pk_smem = 4096 * 4 + 4096 * 8 + 32;   // 49184 (knn superset of precA)
    const int mlp_smem = (64 * AKS * 2 + 4096 + 8192 + 64 + 128 + 64 * 5 + 1024) * 4;
    const int fps_smem = Nf * 3 * 4 + 2 * 32 * 8;   // 49664
    cudaFuncSetAttribute(pk_kernel, cudaFuncAttributeMaxDynamicSharedMemorySize, pk_smem);
    cudaFuncSetAttribute(mlp_kernel, cudaFuncAttributeMaxDynamicSharedMemorySize, mlp_smem);
    cudaFuncSetAttribute(fps_kernel, cudaFuncAttributeMaxDynamicSharedMemorySize, fps_smem);

    prep_kernel<<<64, 256>>>(pos,
                             W0, b0, gg0, be0, rm0, rv0,
                             W1, b1, gg1, be1, rm1, rv1,
                             W2, b2, gg2, be2, rm2, rv2);
    fps_kernel<<<BZf, 1024, fps_smem>>>(pos, sampled);
    pk_kernel<<<PKA + BZf * NSf, 256, pk_smem>>>(x, pos, sampled);
    mlp_kernel<<<BZf * NSf, 128, mlp_smem>>>(pos, sampled, out);
}

// round 5
// speedup vs baseline: 1.9056x; 1.2234x over previous
#include <cuda_runtime.h>
#include <cstdint>

#define BZf 8
#define Nf 4096
#define CFf 64
#define NSf 1024
#define Kf 64

typedef unsigned long long u64;

// ---------------- scratch (device globals; no allocation) ----------------
__device__ __align__(16) float g_W0f[67 * 64];
__device__ __align__(16) float g_b0f[64];
__device__ __align__(16) float g_W1f[64 * 64];
__device__ __align__(16) float g_b1f[64];
__device__ __align__(16) float g_W2f[64 * 128];
__device__ __align__(16) float g_b2f[128];
__device__ float g_pp[BZf * Nf];
__device__ __align__(16) float g_A[BZf * Nf * 64];  // 8 MB: per-point x·W0'[3:] + b0'
__device__ int   g_knn_idx[BZf * NSf * Kf];         // 2 MB
__device__ float g_knn_dist[BZf * NSf * Kf];        // 2 MB

// ---------------- packed fp32x2 helpers (sm_103a) ----------------
__device__ __forceinline__ void ffma2(u64& acc, u64 a, u64 b) {
    asm("fma.rn.f32x2 %0, %1, %2, %0;" : "+l"(acc) : "l"(a), "l"(b));
}
__device__ __forceinline__ u64 add2(u64 a, u64 b) {
    u64 r;
    asm("add.rn.f32x2 %0, %1, %2;" : "=l"(r) : "l"(a), "l"(b));
    return r;
}
__device__ __forceinline__ u64 mul2(u64 a, u64 b) {
    u64 r;
    asm("mul.rn.f32x2 %0, %1, %2;" : "=l"(r) : "l"(a), "l"(b));
    return r;
}
__device__ __forceinline__ u64 dup2(float v) {
    u64 r;
    unsigned int u = __float_as_uint(v);
    asm("mov.b64 %0, {%1, %1};" : "=l"(r) : "r"(u));
    return r;
}
__device__ __forceinline__ u64 pack2(float lo, float hi) {
    u64 r;
    asm("mov.b64 %0, {%1, %2};" : "=l"(r) : "f"(lo), "f"(hi));
    return r;
}
__device__ __forceinline__ float2 unpack2(u64 v) {
    float2 f;
    asm("mov.b64 {%0, %1}, %2;" : "=f"(f.x), "=f"(f.y) : "l"(v));
    return f;
}

// ---------------- prep: fold BN into weights + per-point squared norms ----------------
__global__ void prep_kernel(const float* pos,
                            const float* W0, const float* b0, const float* gg0, const float* be0,
                            const float* rm0, const float* rv0,
                            const float* W1, const float* b1, const float* gg1, const float* be1,
                            const float* rm1, const float* rv1,
                            const float* W2, const float* b2, const float* gg2, const float* be2,
                            const float* rm2, const float* rv2) {
    int t = blockIdx.x * blockDim.x + threadIdx.x;
    int stride = gridDim.x * blockDim.x;
    for (int i = t; i < 67 * 64; i += stride) {
        int c = i & 63;
        float s = gg0[c] / sqrtf(rv0[c] + 1e-5f);
        g_W0f[i] = W0[i] * s;
    }
    for (int c = t; c < 64; c += stride) {
        float s = gg0[c] / sqrtf(rv0[c] + 1e-5f);
        g_b0f[c] = (b0[c] - rm0[c]) * s + be0[c];
    }
    for (int i = t; i < 64 * 64; i += stride) {
        int c = i & 63;
        float s = gg1[c] / sqrtf(rv1[c] + 1e-5f);
        g_W1f[i] = W1[i] * s;
    }
    for (int c = t; c < 64; c += stride) {
        float s = gg1[c] / sqrtf(rv1[c] + 1e-5f);
        g_b1f[c] = (b1[c] - rm1[c]) * s + be1[c];
    }
    for (int i = t; i < 64 * 128; i += stride) {
        int c = i & 127;
        float s = gg2[c] / sqrtf(rv2[c] + 1e-5f);
        g_W2f[i] = W2[i] * s;
    }
    for (int c = t; c < 128; c += stride) {
        float s = gg2[c] / sqrtf(rv2[c] + 1e-5f);
        g_b2f[c] = (b2[c] - rm2[c]) * s + be2[c];
    }
    for (int i = t; i < BZf * Nf; i += stride) {
        float x = pos[i * 3], y = pos[i * 3 + 1], z = pos[i * 3 + 2];
        g_pp[i] = __fadd_rn(__fadd_rn(__fmul_rn(x, x), __fmul_rn(y, y)), __fmul_rn(z, z));
    }
}

// ---------------- FPS: packed f32x2 distances + REDUX argmax (exact ties) ----------
__global__ __launch_bounds__(1024) void fps_kernel(const float* pos, float* sampled) {
    extern __shared__ unsigned char fsm[];
    float* spx = (float*)fsm;                 // 4096
    float* spy = spx + Nf;                    // 4096
    float* spz = spy + Nf;                    // 4096
    u64* red = (u64*)(spz + Nf);              // 2*32

    int b = blockIdx.x;
    int t = threadIdx.x;
    int lane = t & 31;
    int w = t >> 5;
    float dist[4];
    u64 pxp[2], pyp[2], pzp[2];
    {
        float px[4], py[4], pz[4];
#pragma unroll
        for (int r = 0; r < 4; r++) {
            int i = t + (r << 10);
            const float* p = &pos[(b * Nf + i) * 3];
            float X = p[0], Y = p[1], Z = p[2];
            px[r] = X; py[r] = Y; pz[r] = Z;
            spx[i] = X; spy[i] = Y; spz[i] = Z;
            dist[r] = 1e10f;
        }
        pxp[0] = pack2(px[0], px[1]); pxp[1] = pack2(px[2], px[3]);
        pyp[0] = pack2(py[0], py[1]); pyp[1] = pack2(py[2], py[3]);
        pzp[0] = pack2(pz[0], pz[1]); pzp[1] = pack2(pz[2], pz[3]);
    }
    if (t == 0) {
        const float* p = &pos[b * Nf * 3];
        float* o = &sampled[b * NSf * 3];
        o[0] = p[0]; o[1] = p[1]; o[2] = p[2];
    }
    __syncthreads();
    float cx = spx[0], cy = spy[0], cz = spz[0];
    int parity = 0;

    for (int s = 0; s < NSf - 1; s++) {
        u64 ncx = dup2(-cx), ncy = dup2(-cy), ncz = dup2(-cz);
#pragma unroll
        for (int p = 0; p < 2; p++) {
            u64 dx = add2(pxp[p], ncx);
            u64 dy = add2(pyp[p], ncy);
            u64 dz = add2(pzp[p], ncz);
            u64 xx = mul2(dx, dx);
            u64 yy = mul2(dy, dy);
            u64 zz = mul2(dz, dz);
            u64 dd = add2(add2(xx, yy), zz);
            float2 f = unpack2(dd);
            dist[2 * p] = fminf(dist[2 * p], f.x);
            dist[2 * p + 1] = fminf(dist[2 * p + 1], f.y);
        }
        // max of nonneg floats == max of their bit patterns (alu pipe)
        unsigned int u0 = __float_as_uint(dist[0]), u1 = __float_as_uint(dist[1]);
        unsigned int u2 = __float_as_uint(dist[2]), u3 = __float_as_uint(dist[3]);
        unsigned int mb = max(max(u0, u1), max(u2, u3));
        unsigned int wm = __reduce_max_sync(0xffffffffu, mb);
        // first-match (lowest r) within the thread, ~idx-max across lanes -> global min idx
        unsigned int cand = 0u;
        if (u3 == wm) cand = ~(unsigned int)(t + 3072);
        if (u2 == wm) cand = ~(unsigned int)(t + 2048);
        if (u1 == wm) cand = ~(unsigned int)(t + 1024);
        if (u0 == wm) cand = ~(unsigned int)t;
        unsigned int wi = __reduce_max_sync(0xffffffffu, cand);
        if (lane == 0)
            red[parity * 32 + w] = ((u64)wm << 32) | (u64)wi;
        __syncthreads();
        u64 v = red[parity * 32 + lane];
        unsigned int d2 = (unsigned int)(v >> 32);
        unsigned int i2 = (unsigned int)v;
        unsigned int hi = __reduce_max_sync(0xffffffffu, d2);
        unsigned int c2 = (d2 == hi) ? i2 : 0u;
        unsigned int gi = __reduce_max_sync(0xffffffffu, c2);
        int nidx = (int)(~gi);
        cx = spx[nidx]; cy = spy[nidx]; cz = spz[nidx];
        if (t == 0) {
            float* o = &sampled[(b * NSf + s + 1) * 3];
            o[0] = cx; o[1] = cy; o[2] = cz;
        }
        parity ^= 1;
    }
}

// ---------------- merged precA + kNN (branch by block range) ----------------
#define PKA 2048  // precA blocks (16 rows each)
__global__ __launch_bounds__(256) void pk_kernel(const float* x, const float* pos,
                                                 const float* sampled) {
    extern __shared__ unsigned char smem[];
    int t = threadIdx.x;
    if (blockIdx.x < PKA) {
        // ---- precA: A = x . W0'[3:67] + b0', 16 rows per block ----
        float* sx = (float*)smem;  // 16*64
        int base = blockIdx.x * 16;
        for (int i = t; i < 16 * 64; i += 256) sx[i] = x[base * 64 + i];
        __syncthreads();
        int c = t & 63, rg = t >> 6;  // 4 row-groups x 4 rows
        float bv = g_b0f[c];
        float a0 = bv, a1 = bv, a2 = bv, a3 = bv;
        const float* sxr = &sx[rg * 4 * 64];
#pragma unroll 8
        for (int i = 0; i < 64; i++) {
            float wv = g_W0f[(3 + i) * 64 + c];
            a0 = fmaf(sxr[i], wv, a0);
            a1 = fmaf(sxr[64 + i], wv, a1);
            a2 = fmaf(sxr[128 + i], wv, a2);
            a3 = fmaf(sxr[192 + i], wv, a3);
        }
        int r0 = base + rg * 4;
        g_A[(r0 + 0) * 64 + c] = a0;
        g_A[(r0 + 1) * 64 + c] = a1;
        g_A[(r0 + 2) * 64 + c] = a2;
        g_A[(r0 + 3) * 64 + c] = a3;
        return;
    }
    // ---- kNN top-64 per centroid (exact top_k tie semantics) ----
    float* sd = (float*)smem;                                   // 4096 f
    u64* cand = (u64*)(smem + 4096 * 4);                        // 4096 u64
    int* scnt = (int*)(smem + 4096 * 4 + 4096 * 8);             // 6 ints
    __shared__ float cxs, cys, czs, sss;
    int g = blockIdx.x - PKA;
    int b = g >> 10;
    if (t == 0) {
        float cx = sampled[g * 3], cy = sampled[g * 3 + 1], cz = sampled[g * 3 + 2];
        cxs = cx; cys = cy; czs = cz;
        sss = __fadd_rn(__fadd_rn(__fmul_rn(cx, cx), __fmul_rn(cy, cy)), __fmul_rn(cz, cz));
    }
    if (t < 6) scnt[t] = 0;
    __syncthreads();
    float sx = cxs, sy = cys, sz = czs, ss = sss;
    const float T0 = 0.18f, T1 = 0.25f, T2 = 0.35f, T3 = 0.55f;
    int c0 = 0, c1 = 0, c2 = 0, c3 = 0;
    const float* pb = &pos[b * Nf * 3];
    const float* ppb = &g_pp[b * Nf];
    for (int p = t; p < Nf; p += 256) {
        float X = pb[p * 3], Y = pb[p * 3 + 1], Z = pb[p * 3 + 2];
        float dot = __fadd_rn(__fadd_rn(__fmul_rn(sx, X), __fmul_rn(sy, Y)), __fmul_rn(sz, Z));
        float d2 = __fsub_rn(__fadd_rn(ss, ppb[p]), __fmul_rn(2.0f, dot));
        float d = sqrtf(fmaxf(d2, 0.0f));
        sd[p] = d;
        c0 += (d <= T0); c1 += (d <= T1); c2 += (d <= T2); c3 += (d <= T3);
    }
    atomicAdd(&scnt[0], c0);
    atomicAdd(&scnt[1], c1);
    atomicAdd(&scnt[2], c2);
    atomicAdd(&scnt[3], c3);
    __syncthreads();
    float thr;
    if (scnt[0] >= Kf) thr = T0;
    else if (scnt[1] >= Kf) thr = T1;
    else if (scnt[2] >= Kf) thr = T2;
    else if (scnt[3] >= Kf) thr = T3;
    else thr = 1e30f;
    for (int p = t; p < Nf; p += 256) {
        float d = sd[p];
        if (d <= thr) {
            int slot = atomicAdd(&scnt[5], 1);
            cand[slot] = ((u64)__float_as_uint(d) << 32) | (unsigned int)p;
        }
    }
    __syncthreads();
    int cnt = scnt[5];
    int P = 128;
    while (P < cnt) P <<= 1;
    for (int i = t; i < P; i += 256)
        if (i >= cnt) cand[i] = 0xffffffffffffffffull;
    __syncthreads();
    for (int k2 = 2; k2 <= P; k2 <<= 1) {
        for (int j = k2 >> 1; j > 0; j >>= 1) {
            for (int i = t; i < P; i += 256) {
                int ij = i ^ j;
                if (ij > i) {
                    u64 a = cand[i], bb = cand[ij];
                    bool up = ((i & k2) == 0);
                    if ((a > bb) == up) { cand[i] = bb; cand[ij] = a; }
                }
            }
            __syncthreads();
        }
    }
    if (t < Kf) {
        u64 key = cand[t];
        g_knn_idx[g * Kf + t] = (int)(key & 0xffffffffull);
        g_knn_dist[g * Kf + t] = __uint_as_float((unsigned int)(key >> 32));
    }
}

// ---- fused MLP (FFMA2) + masked max-pool; low smem (39KB) for 5 blocks/SM ----
#define AKS 68  // activation row stride ([c][k] layout), 16B-aligned rows
__global__ __launch_bounds__(128) void mlp_kernel(const float* pos, const float* sampled, float* out) {
    extern __shared__ unsigned char smem[];
    float* act = (float*)smem;             // 64*68 (reused: layer1 out, then layer2 out)
    float* sW1 = act + 64 * AKS;           // 4096
    float* sB1 = sW1 + 4096;               // 64
    float* sB2 = sB1 + 64;                 // 128
    float* sdpx = sB2 + 128;               // 64
    float* sdpy = sdpx + 64;               // 64
    float* sdpz = sdpy + 64;               // 64
    int* sidx = (int*)(sdpz + 64);         // 64
    int* smask = sidx + 64;                // 64
    float* pmax = (float*)(smask + 64);    // 8*128

    int g = blockIdx.x;
    int b = g >> 10;
    int t = threadIdx.x;
    int w = t >> 5, lane = t & 31;
    int ksub = lane >> 4;                  // 0/1
    int k0 = w * 16 + ksub * 8;            // this thread's 8 k's
    int cL = lane & 15;

    for (int i = t; i < 4096; i += 128) sW1[i] = g_W1f[i];
    if (t < 64) sB1[t] = g_b1f[t];
    if (t < 128) sB2[t] = g_b2f[t];
    if (t < 64) {
        int idx = g_knn_idx[g * Kf + t];
        float d = g_knn_dist[g * Kf + t];
        const float* p = &pos[(b * Nf + idx) * 3];
        float ccx = sampled[g * 3], ccy = sampled[g * 3 + 1], ccz = sampled[g * 3 + 2];
        sdpx[t] = p[0] - ccx;
        sdpy[t] = p[1] - ccy;
        sdpz[t] = p[2] - ccz;
        sidx[t] = idx;
        smask[t] = (d <= 0.2f) ? 1 : 0;
    }
    __syncthreads();

    // layer 1 (input 67 -> 64): A already holds x-part + bias; add dp part.
    {
        int c = t & 63;
        float w0 = g_W0f[c], w1 = g_W0f[64 + c], w2 = g_W0f[128 + c];
        for (int e = t; e < 4096; e += 128) {
            int k = e >> 6;
            float a = g_A[(b * Nf + sidx[k]) * 64 + c];
            float z = fmaf(sdpx[k], w0, a);
            z = fmaf(sdpy[k], w1, z);
            z = fmaf(sdpz[k], w2, z);
            act[c * AKS + k] = fmaxf(z, 0.0f);
        }
    }
    __syncthreads();

    // layer 2 (64 -> 64): thread tile 8k x 4c; result staged in regs, then act reused
    u64 acc2[4][4];
    {
        int cc0 = cL * 4;
#pragma unroll
        for (int j = 0; j < 4; j++)
#pragma unroll
            for (int q = 0; q < 4; q++) acc2[j][q] = 0ull;
        for (int ci = 0; ci < 64; ci++) {
            const u64* ar = (const u64*)&act[ci * AKS + k0];
            u64 a0 = ar[0], a1 = ar[1], a2 = ar[2], a3 = ar[3];
            float4 wv = *(const float4*)&sW1[ci * 64 + cc0];
            u64 w0 = dup2(wv.x), w1 = dup2(wv.y), w2 = dup2(wv.z), w3 = dup2(wv.w);
            ffma2(acc2[0][0], a0, w0); ffma2(acc2[1][0], a1, w0);
            ffma2(acc2[2][0], a2, w0); ffma2(acc2[3][0], a3, w0);
            ffma2(acc2[0][1], a0, w1); ffma2(acc2[1][1], a1, w1);
            ffma2(acc2[2][1], a2, w1); ffma2(acc2[3][1], a3, w1);
            ffma2(acc2[0][2], a0, w2); ffma2(acc2[1][2], a1, w2);
            ffma2(acc2[2][2], a2, w2); ffma2(acc2[3][2], a3, w2);
            ffma2(acc2[0][3], a0, w3); ffma2(acc2[1][3], a1, w3);
            ffma2(acc2[2][3], a2, w3); ffma2(acc2[3][3], a3, w3);
        }
    }
    __syncthreads();  // all reads of layer-1 act done; safe to overwrite
    {
        int cc0 = cL * 4;
#pragma unroll
        for (int cq = 0; cq < 4; cq++) {
            float bb = sB1[cc0 + cq];
#pragma unroll
            for (int kp = 0; kp < 4; kp++) {
                float2 v = unpack2(acc2[kp][cq]);
                float2 r;
                r.x = fmaxf(v.x + bb, 0.0f);
                r.y = fmaxf(v.y + bb, 0.0f);
                *(float2*)&act[(cc0 + cq) * AKS + k0 + 2 * kp] = r;
            }
        }
    }
    __syncthreads();

    // layer 3 (64 -> 128) + masked max pool: thread tile 8k x 8c; W2 via LDG (L1-resident)
    {
        int cc0 = cL * 8;
        u64 acc[4][8];
#pragma unroll
        for (int j = 0; j < 4; j++)
#pragma unroll
            for (int q = 0; q < 8; q++) acc[j][q] = 0ull;
        const float4* W2v = (const float4*)g_W2f;  // 32 float4 per ci row
#pragma unroll 2
        for (int ci = 0; ci < 64; ci++) {
            const u64* ar = (const u64*)&act[ci * AKS + k0];
            u64 a0 = ar[0], a1 = ar[1], a2 = ar[2], a3 = ar[3];
            float4 wa = __ldg(&W2v[ci * 32 + cL * 2]);
            float4 wb = __ldg(&W2v[ci * 32 + cL * 2 + 1]);
            u64 w0 = dup2(wa.x), w1 = dup2(wa.y), w2 = dup2(wa.z), w3 = dup2(wa.w);
            u64 w4 = dup2(wb.x), w5 = dup2(wb.y), w6 = dup2(wb.z), w7 = dup2(wb.w);
            ffma2(acc[0][0], a0, w0); ffma2(acc[1][0], a1, w0);
            ffma2(acc[2][0], a2, w0); ffma2(acc[3][0], a3, w0);
            ffma2(acc[0][1], a0, w1); ffma2(acc[1][1], a1, w1);
            ffma2(acc[2][1], a2, w1); ffma2(acc[3][1], a3, w1);
            ffma2(acc[0][2], a0, w2); ffma2(acc[1][2], a1, w2);
            ffma2(acc[2][2], a2, w2); ffma2(acc[3][2], a3, w2);
            ffma2(acc[0][3], a0, w3); ffma2(acc[1][3], a1, w3);
            ffma2(acc[2][3], a2, w3); ffma2(acc[3][3], a3, w3);
            ffma2(acc[0][4], a0, w4); ffma2(acc[1][4], a1, w4);
            ffma2(acc[2][4], a2, w4); ffma2(acc[3][4], a3, w4);
            ffma2(acc[0][5], a0, w5); ffma2(acc[1][5], a1, w5);
            ffma2(acc[2][5], a2, w5); ffma2(acc[3][5], a3, w5);
            ffma2(acc[0][6], a0, w6); ffma2(acc[1][6], a1, w6);
            ffma2(acc[2][6], a2, w6); ffma2(acc[3][6], a3, w6);
            ffma2(acc[0][7], a0, w7); ffma2(acc[1][7], a1, w7);
            ffma2(acc[2][7], a2, w7); ffma2(acc[3][7], a3, w7);
        }
#pragma unroll
        for (int cq = 0; cq < 8; cq++) {
            float bb = sB2[cc0 + cq];
            float m = -1e8f;
#pragma unroll
            for (int kp = 0; kp < 4; kp++) {
                float2 v = unpack2(acc[kp][cq]);
                float h0 = fmaxf(v.x + bb, 0.0f);
                float h1 = fmaxf(v.y + bb, 0.0f);
                float q0 = smask[k0 + 2 * kp] ? h0 : -1e8f;
                float q1 = smask[k0 + 2 * kp + 1] ? h1 : -1e8f;
                m = fmaxf(m, fmaxf(q0, q1));
            }
            pmax[(w * 2 + ksub) * 128 + cc0 + cq] = m;
        }
    }
    __syncthreads();
    if (t < 128) {
        float m = pmax[t];
#pragma unroll
        for (int q = 1; q < 8; q++) m = fmaxf(m, pmax[q * 128 + t]);
        out[g * 128 + t] = m;
    }
}

// ---------------- launch ----------------
extern "C" void kernel_launch(void* const* d_in, const int* in_sizes, int n_in,
                              void* d_out, int out_size) {
    (void)in_sizes; (void)n_in; (void)out_size;
    const float* x = (const float*)d_in[0];
    const float* pos = (const float*)d_in[1];
    const float* W0 = (const float*)d_in[2];
    const float* b0 = (const float*)d_in[3];
    const float* gg0 = (const float*)d_in[4];
    const float* be0 = (const float*)d_in[5];
    const float* rm0 = (const float*)d_in[6];
    const float* rv0 = (const float*)d_in[7];
    const float* W1 = (const float*)d_in[8];
    const float* b1 = (const float*)d_in[9];
    const float* gg1 = (const float*)d_in[10];
    const float* be1 = (const float*)d_in[11];
    const float* rm1 = (const float*)d_in[12];
    const float* rv1 = (const float*)d_in[13];
    const float* W2 = (const float*)d_in[14];
    const float* b2 = (const float*)d_in[15];
    const float* gg2 = (const float*)d_in[16];
    const float* be2 = (const float*)d_in[17];
    const float* rm2 = (const float*)d_in[18];
    const float* rv2 = (const float*)d_in[19];

    float* out = (float*)d_out;
    float* sampled = out + (size_t)BZf * NSf * 128;

    const int pk_smem = 4096 * 4 + 4096 * 8 + 32;   // 49184 (knn superset of precA)
    const int mlp_smem = (64 * AKS + 4096 + 64 + 128 + 64 * 5 + 1024) * 4;  // ~39.4KB
    const int fps_smem = Nf * 3 * 4 + 2 * 32 * 8;   // 49664
    cudaFuncSetAttribute(pk_kernel, cudaFuncAttributeMaxDynamicSharedMemorySize, pk_smem);
    cudaFuncSetAttribute(mlp_kernel, cudaFuncAttributeMaxDynamicSharedMemorySize, mlp_smem);
    cudaFuncSetAttribute(fps_kernel, cudaFuncAttributeMaxDynamicSharedMemorySize, fps_smem);

    prep_kernel<<<64, 256>>>(pos,
                             W0, b0, gg0, be0, rm0, rv0,
                             W1, b1, gg1, be1, rm1, rv1,
                             W2, b2, gg2, be2, rm2, rv2);
    fps_kernel<<<BZf, 1024, fps_smem>>>(pos, sampled);
    pk_kernel<<<PKA + BZf * NSf, 256, pk_smem>>>(x, pos, sampled);
    mlp_kernel<<<BZf * NSf, 128, mlp_smem>>>(pos, sampled, out);
}

// round 6
// speedup vs baseline: 1.9557x; 1.0263x over previous
#include <cuda_runtime.h>
#include <cstdint>

#define BZf 8
#define Nf 4096
#define CFf 64
#define NSf 1024
#define Kf 64

typedef unsigned long long u64;

// ---------------- scratch (device globals; no allocation) ----------------
__device__ __align__(16) float g_W0f[67 * 64];
__device__ __align__(16) float g_b0f[64];
__device__ __align__(16) float g_W1f[64 * 64];
__device__ __align__(16) float g_b1f[64];
__device__ __align__(16) float g_W2f[64 * 128];
__device__ __align__(16) float g_b2f[128];
__device__ float g_pp[BZf * Nf];
__device__ __align__(16) float g_A[BZf * Nf * 64];  // 8 MB: per-point x·W0'[3:] + b0'
__device__ int   g_knn_idx[BZf * NSf * Kf];         // 2 MB
__device__ float g_knn_dist[BZf * NSf * Kf];        // 2 MB

// ---------------- packed fp32x2 helpers (sm_103a) ----------------
__device__ __forceinline__ void ffma2(u64& acc, u64 a, u64 b) {
    asm("fma.rn.f32x2 %0, %1, %2, %0;" : "+l"(acc) : "l"(a), "l"(b));
}
__device__ __forceinline__ u64 add2(u64 a, u64 b) {
    u64 r;
    asm("add.rn.f32x2 %0, %1, %2;" : "=l"(r) : "l"(a), "l"(b));
    return r;
}
__device__ __forceinline__ u64 mul2(u64 a, u64 b) {
    u64 r;
    asm("mul.rn.f32x2 %0, %1, %2;" : "=l"(r) : "l"(a), "l"(b));
    return r;
}
__device__ __forceinline__ u64 dup2(float v) {
    u64 r;
    unsigned int u = __float_as_uint(v);
    asm("mov.b64 %0, {%1, %1};" : "=l"(r) : "r"(u));
    return r;
}
__device__ __forceinline__ u64 pack2(float lo, float hi) {
    u64 r;
    asm("mov.b64 %0, {%1, %2};" : "=l"(r) : "f"(lo), "f"(hi));
    return r;
}
__device__ __forceinline__ float2 unpack2(u64 v) {
    float2 f;
    asm("mov.b64 {%0, %1}, %2;" : "=f"(f.x), "=f"(f.y) : "l"(v));
    return f;
}

// ---------------- prep: fold BN into weights + per-point squared norms ----------------
__global__ void prep_kernel(const float* pos,
                            const float* W0, const float* b0, const float* gg0, const float* be0,
                            const float* rm0, const float* rv0,
                            const float* W1, const float* b1, const float* gg1, const float* be1,
                            const float* rm1, const float* rv1,
                            const float* W2, const float* b2, const float* gg2, const float* be2,
                            const float* rm2, const float* rv2) {
    int t = blockIdx.x * blockDim.x + threadIdx.x;
    int stride = gridDim.x * blockDim.x;
    for (int i = t; i < 67 * 64; i += stride) {
        int c = i & 63;
        float s = gg0[c] / sqrtf(rv0[c] + 1e-5f);
        g_W0f[i] = W0[i] * s;
    }
    for (int c = t; c < 64; c += stride) {
        float s = gg0[c] / sqrtf(rv0[c] + 1e-5f);
        g_b0f[c] = (b0[c] - rm0[c]) * s + be0[c];
    }
    for (int i = t; i < 64 * 64; i += stride) {
        int c = i & 63;
        float s = gg1[c] / sqrtf(rv1[c] + 1e-5f);
        g_W1f[i] = W1[i] * s;
    }
    for (int c = t; c < 64; c += stride) {
        float s = gg1[c] / sqrtf(rv1[c] + 1e-5f);
        g_b1f[c] = (b1[c] - rm1[c]) * s + be1[c];
    }
    for (int i = t; i < 64 * 128; i += stride) {
        int c = i & 127;
        float s = gg2[c] / sqrtf(rv2[c] + 1e-5f);
        g_W2f[i] = W2[i] * s;
    }
    for (int c = t; c < 128; c += stride) {
        float s = gg2[c] / sqrtf(rv2[c] + 1e-5f);
        g_b2f[c] = (b2[c] - rm2[c]) * s + be2[c];
    }
    for (int i = t; i < BZf * Nf; i += stride) {
        float x = pos[i * 3], y = pos[i * 3 + 1], z = pos[i * 3 + 2];
        g_pp[i] = __fadd_rn(__fadd_rn(__fmul_rn(x, x), __fmul_rn(y, y)), __fmul_rn(z, z));
    }
}

// ---------------- FPS: packed f32x2 distances + REDUX argmax (exact ties) ----------
__global__ __launch_bounds__(1024) void fps_kernel(const float* pos, float* sampled) {
    extern __shared__ unsigned char fsm[];
    float* spx = (float*)fsm;                 // 4096
    float* spy = spx + Nf;                    // 4096
    float* spz = spy + Nf;                    // 4096
    u64* red = (u64*)(spz + Nf);              // 2*32

    int b = blockIdx.x;
    int t = threadIdx.x;
    int lane = t & 31;
    int w = t >> 5;
    float dist[4];
    u64 pxp[2], pyp[2], pzp[2];
    {
        float px[4], py[4], pz[4];
#pragma unroll
        for (int r = 0; r < 4; r++) {
            int i = t + (r << 10);
            const float* p = &pos[(b * Nf + i) * 3];
            float X = p[0], Y = p[1], Z = p[2];
            px[r] = X; py[r] = Y; pz[r] = Z;
            spx[i] = X; spy[i] = Y; spz[i] = Z;
            dist[r] = 1e10f;
        }
        pxp[0] = pack2(px[0], px[1]); pxp[1] = pack2(px[2], px[3]);
        pyp[0] = pack2(py[0], py[1]); pyp[1] = pack2(py[2], py[3]);
        pzp[0] = pack2(pz[0], pz[1]); pzp[1] = pack2(pz[2], pz[3]);
    }
    if (t == 0) {
        const float* p = &pos[b * Nf * 3];
        float* o = &sampled[b * NSf * 3];
        o[0] = p[0]; o[1] = p[1]; o[2] = p[2];
    }
    __syncthreads();
    float cx = spx[0], cy = spy[0], cz = spz[0];
    int parity = 0;

    for (int s = 0; s < NSf - 1; s++) {
        u64 ncx = dup2(-cx), ncy = dup2(-cy), ncz = dup2(-cz);
#pragma unroll
        for (int p = 0; p < 2; p++) {
            u64 dx = add2(pxp[p], ncx);
            u64 dy = add2(pyp[p], ncy);
            u64 dz = add2(pzp[p], ncz);
            u64 xx = mul2(dx, dx);
            u64 yy = mul2(dy, dy);
            u64 zz = mul2(dz, dz);
            u64 dd = add2(add2(xx, yy), zz);
            float2 f = unpack2(dd);
            dist[2 * p] = fminf(dist[2 * p], f.x);
            dist[2 * p + 1] = fminf(dist[2 * p + 1], f.y);
        }
        // max of nonneg floats == max of their bit patterns (alu pipe)
        unsigned int u0 = __float_as_uint(dist[0]), u1 = __float_as_uint(dist[1]);
        unsigned int u2 = __float_as_uint(dist[2]), u3 = __float_as_uint(dist[3]);
        unsigned int mb = max(max(u0, u1), max(u2, u3));
        unsigned int wm = __reduce_max_sync(0xffffffffu, mb);
        // first-match (lowest r) within the thread, ~idx-max across lanes -> global min idx
        unsigned int cand = 0u;
        if (u3 == wm) cand = ~(unsigned int)(t + 3072);
        if (u2 == wm) cand = ~(unsigned int)(t + 2048);
        if (u1 == wm) cand = ~(unsigned int)(t + 1024);
        if (u0 == wm) cand = ~(unsigned int)t;
        unsigned int wi = __reduce_max_sync(0xffffffffu, cand);
        if (lane == 0)
            red[parity * 32 + w] = ((u64)wm << 32) | (u64)wi;
        __syncthreads();
        u64 v = red[parity * 32 + lane];
        unsigned int d2 = (unsigned int)(v >> 32);
        unsigned int i2 = (unsigned int)v;
        unsigned int hi = __reduce_max_sync(0xffffffffu, d2);
        unsigned int c2 = (d2 == hi) ? i2 : 0u;
        unsigned int gi = __reduce_max_sync(0xffffffffu, c2);
        int nidx = (int)(~gi);
        cx = spx[nidx]; cy = spy[nidx]; cz = spz[nidx];
        if (t == 0) {
            float* o = &sampled[(b * NSf + s + 1) * 3];
            o[0] = cx; o[1] = cy; o[2] = cz;
        }
        parity ^= 1;
    }
}

// ---------------- merged precA + kNN (branch by block range) ----------------
#define PKA 2048  // precA blocks (16 rows each)
__global__ __launch_bounds__(256) void pk_kernel(const float* x, const float* pos,
                                                 const float* sampled) {
    extern __shared__ unsigned char smem[];
    int t = threadIdx.x;
    if (blockIdx.x < PKA) {
        // ---- precA: A = x . W0'[3:67] + b0', 16 rows per block ----
        float* sx = (float*)smem;  // 16*64
        int base = blockIdx.x * 16;
        for (int i = t; i < 16 * 64; i += 256) sx[i] = x[base * 64 + i];
        __syncthreads();
        int c = t & 63, rg = t >> 6;  // 4 row-groups x 4 rows
        float bv = g_b0f[c];
        float a0 = bv, a1 = bv, a2 = bv, a3 = bv;
        const float* sxr = &sx[rg * 4 * 64];
#pragma unroll 8
        for (int i = 0; i < 64; i++) {
            float wv = g_W0f[(3 + i) * 64 + c];
            a0 = fmaf(sxr[i], wv, a0);
            a1 = fmaf(sxr[64 + i], wv, a1);
            a2 = fmaf(sxr[128 + i], wv, a2);
            a3 = fmaf(sxr[192 + i], wv, a3);
        }
        int r0 = base + rg * 4;
        g_A[(r0 + 0) * 64 + c] = a0;
        g_A[(r0 + 1) * 64 + c] = a1;
        g_A[(r0 + 2) * 64 + c] = a2;
        g_A[(r0 + 3) * 64 + c] = a3;
        return;
    }
    // ---- kNN top-64 per centroid; d^2 prefilter, sqrt only survivors ----
    float* sd = (float*)smem;                                   // 4096 f (d^2)
    u64* cand = (u64*)(smem + 4096 * 4);                        // 4096 u64
    int* scnt = (int*)(smem + 4096 * 4 + 4096 * 8);             // 6 ints
    __shared__ float cxs, cys, czs, sss;
    int g = blockIdx.x - PKA;
    int b = g >> 10;
    if (t == 0) {
        float cx = sampled[g * 3], cy = sampled[g * 3 + 1], cz = sampled[g * 3 + 2];
        cxs = cx; cys = cy; czs = cz;
        sss = __fadd_rn(__fadd_rn(__fmul_rn(cx, cx), __fmul_rn(cy, cy)), __fmul_rn(cz, cz));
    }
    if (t < 6) scnt[t] = 0;
    __syncthreads();
    float sx = cxs, sy = cys, sz = czs, ss = sss;
    // squared thresholds, with slack: LO for counting (undercount-safe),
    // HI for collection (superset-safe). Selection stays exact via the sort.
    const float T0L = 0.18f * 0.18f * 0.99999f, T0H = 0.18f * 0.18f * 1.00001f;
    const float T1L = 0.25f * 0.25f * 0.99999f, T1H = 0.25f * 0.25f * 1.00001f;
    const float T2L = 0.35f * 0.35f * 0.99999f, T2H = 0.35f * 0.35f * 1.00001f;
    const float T3L = 0.55f * 0.55f * 0.99999f, T3H = 0.55f * 0.55f * 1.00001f;
    int c0 = 0, c1 = 0, c2 = 0, c3 = 0;
    const float* pb = &pos[b * Nf * 3];
    const float* ppb = &g_pp[b * Nf];
    for (int p = t; p < Nf; p += 256) {
        float X = pb[p * 3], Y = pb[p * 3 + 1], Z = pb[p * 3 + 2];
        float dot = __fadd_rn(__fadd_rn(__fmul_rn(sx, X), __fmul_rn(sy, Y)), __fmul_rn(sz, Z));
        float d2 = __fsub_rn(__fadd_rn(ss, ppb[p]), __fmul_rn(2.0f, dot));
        sd[p] = d2;
        c0 += (d2 <= T0L); c1 += (d2 <= T1L); c2 += (d2 <= T2L); c3 += (d2 <= T3L);
    }
    atomicAdd(&scnt[0], c0);
    atomicAdd(&scnt[1], c1);
    atomicAdd(&scnt[2], c2);
    atomicAdd(&scnt[3], c3);
    __syncthreads();
    float thrsq;
    if (scnt[0] >= Kf) thrsq = T0H;
    else if (scnt[1] >= Kf) thrsq = T1H;
    else if (scnt[2] >= Kf) thrsq = T2H;
    else if (scnt[3] >= Kf) thrsq = T3H;
    else thrsq = 1e30f;
    for (int p = t; p < Nf; p += 256) {
        float d2v = sd[p];
        if (d2v <= thrsq) {
            float d = sqrtf(fmaxf(d2v, 0.0f));  // exact same expr as reference path
            int slot = atomicAdd(&scnt[5], 1);
            cand[slot] = ((u64)__float_as_uint(d) << 32) | (unsigned int)p;
        }
    }
    __syncthreads();
    int cnt = scnt[5];
    int P = 128;
    while (P < cnt) P <<= 1;
    for (int i = t; i < P; i += 256)
        if (i >= cnt) cand[i] = 0xffffffffffffffffull;
    __syncthreads();
    for (int k2 = 2; k2 <= P; k2 <<= 1) {
        for (int j = k2 >> 1; j > 0; j >>= 1) {
            for (int i = t; i < P; i += 256) {
                int ij = i ^ j;
                if (ij > i) {
                    u64 a = cand[i], bb = cand[ij];
                    bool up = ((i & k2) == 0);
                    if ((a > bb) == up) { cand[i] = bb; cand[ij] = a; }
                }
            }
            __syncthreads();
        }
    }
    if (t < Kf) {
        u64 key = cand[t];
        g_knn_idx[g * Kf + t] = (int)(key & 0xffffffffull);
        g_knn_dist[g * Kf + t] = __uint_as_float((unsigned int)(key >> 32));
    }
}

// ---- fused MLP (FFMA2) + masked max-pool; 35.8KB smem + <=85 regs -> 6 blocks/SM ----
#define AKS 68  // activation row stride ([c][k] layout), 16B-aligned rows
__global__ __launch_bounds__(128, 6) void mlp_kernel(const float* pos, const float* sampled,
                                                     float* out) {
    extern __shared__ unsigned char smem[];
    float* act = (float*)smem;             // 64*68 (layer1 out -> layer2 out -> pmax alias)
    float* sW1 = act + 64 * AKS;           // 4096
    float* sB1 = sW1 + 4096;               // 64
    float* sB2 = sB1 + 64;                 // 128
    float* sdpx = sB2 + 128;               // 64
    float* sdpy = sdpx + 64;               // 64
    float* sdpz = sdpy + 64;               // 64
    int* sidx = (int*)(sdpz + 64);         // 64
    int* smask = sidx + 64;                // 64
    float* pmax = act;                     // 8*128, aliased into act after barrier

    int g = blockIdx.x;
    int b = g >> 10;
    int t = threadIdx.x;
    int w = t >> 5, lane = t & 31;
    int ksub = lane >> 4;                  // 0/1
    int k0 = w * 16 + ksub * 8;            // this thread's 8 k's
    int cL = lane & 15;

    for (int i = t; i < 4096; i += 128) sW1[i] = g_W1f[i];
    if (t < 64) sB1[t] = g_b1f[t];
    if (t < 128) sB2[t] = g_b2f[t];
    if (t < 64) {
        int idx = g_knn_idx[g * Kf + t];
        float d = g_knn_dist[g * Kf + t];
        const float* p = &pos[(b * Nf + idx) * 3];
        float ccx = sampled[g * 3], ccy = sampled[g * 3 + 1], ccz = sampled[g * 3 + 2];
        sdpx[t] = p[0] - ccx;
        sdpy[t] = p[1] - ccy;
        sdpz[t] = p[2] - ccz;
        sidx[t] = idx;
        smask[t] = (d <= 0.2f) ? 1 : 0;
    }
    __syncthreads();

    // layer 1 (input 67 -> 64): A already holds x-part + bias; add dp part.
    {
        int c = t & 63;
        float w0 = g_W0f[c], w1 = g_W0f[64 + c], w2 = g_W0f[128 + c];
        for (int e = t; e < 4096; e += 128) {
            int k = e >> 6;
            float a = g_A[(b * Nf + sidx[k]) * 64 + c];
            float z = fmaf(sdpx[k], w0, a);
            z = fmaf(sdpy[k], w1, z);
            z = fmaf(sdpz[k], w2, z);
            act[c * AKS + k] = fmaxf(z, 0.0f);
        }
    }
    __syncthreads();

    // layer 2 (64 -> 64): thread tile 8k x 4c; result staged in regs, then act reused
    u64 acc2[4][4];
    {
        int cc0 = cL * 4;
#pragma unroll
        for (int j = 0; j < 4; j++)
#pragma unroll
            for (int q = 0; q < 4; q++) acc2[j][q] = 0ull;
        for (int ci = 0; ci < 64; ci++) {
            const u64* ar = (const u64*)&act[ci * AKS + k0];
            u64 a0 = ar[0], a1 = ar[1], a2 = ar[2], a3 = ar[3];
            float4 wv = *(const float4*)&sW1[ci * 64 + cc0];
            u64 w0 = dup2(wv.x), w1 = dup2(wv.y), w2 = dup2(wv.z), w3 = dup2(wv.w);
            ffma2(acc2[0][0], a0, w0); ffma2(acc2[1][0], a1, w0);
            ffma2(acc2[2][0], a2, w0); ffma2(acc2[3][0], a3, w0);
            ffma2(acc2[0][1], a0, w1); ffma2(acc2[1][1], a1, w1);
            ffma2(acc2[2][1], a2, w1); ffma2(acc2[3][1], a3, w1);
            ffma2(acc2[0][2], a0, w2); ffma2(acc2[1][2], a1, w2);
            ffma2(acc2[2][2], a2, w2); ffma2(acc2[3][2], a3, w2);
            ffma2(acc2[0][3], a0, w3); ffma2(acc2[1][3], a1, w3);
            ffma2(acc2[2][3], a2, w3); ffma2(acc2[3][3], a3, w3);
        }
    }
    __syncthreads();  // all reads of layer-1 act done; safe to overwrite
    {
        int cc0 = cL * 4;
#pragma unroll
        for (int cq = 0; cq < 4; cq++) {
            float bb = sB1[cc0 + cq];
#pragma unroll
            for (int kp = 0; kp < 4; kp++) {
                float2 v = unpack2(acc2[kp][cq]);
                float2 r;
                r.x = fmaxf(v.x + bb, 0.0f);
                r.y = fmaxf(v.y + bb, 0.0f);
                *(float2*)&act[(cc0 + cq) * AKS + k0 + 2 * kp] = r;
            }
        }
    }
    __syncthreads();

    // layer 3 (64 -> 128) + masked max pool: two passes of 4 channels (halved acc regs)
    float mres[8];
    const float4* W2v = (const float4*)g_W2f;  // 32 float4 per ci row
#pragma unroll 1
    for (int half = 0; half < 2; half++) {
        int cc0 = cL * 8 + half * 4;
        u64 acc[4][4];
#pragma unroll
        for (int j = 0; j < 4; j++)
#pragma unroll
            for (int q = 0; q < 4; q++) acc[j][q] = 0ull;
#pragma unroll 2
        for (int ci = 0; ci < 64; ci++) {
            const u64* ar = (const u64*)&act[ci * AKS + k0];
            u64 a0 = ar[0], a1 = ar[1], a2 = ar[2], a3 = ar[3];
            float4 wv = __ldg(&W2v[ci * 32 + cL * 2 + half]);
            u64 w0 = dup2(wv.x), w1 = dup2(wv.y), w2 = dup2(wv.z), w3 = dup2(wv.w);
            ffma2(acc[0][0], a0, w0); ffma2(acc[1][0], a1, w0);
            ffma2(acc[2][0], a2, w0); ffma2(acc[3][0], a3, w0);
            ffma2(acc[0][1], a0, w1); ffma2(acc[1][1], a1, w1);
            ffma2(acc[2][1], a2, w1); ffma2(acc[3][1], a3, w1);
            ffma2(acc[0][2], a0, w2); ffma2(acc[1][2], a1, w2);
            ffma2(acc[2][2], a2, w2); ffma2(acc[3][2], a3, w2);
            ffma2(acc[0][3], a0, w3); ffma2(acc[1][3], a1, w3);
            ffma2(acc[2][3], a2, w3); ffma2(acc[3][3], a3, w3);
        }
#pragma unroll
        for (int cq = 0; cq < 4; cq++) {
            float bb = sB2[cc0 + cq];
            float m = -1e8f;
#pragma unroll
            for (int kp = 0; kp < 4; kp++) {
                float2 v = unpack2(acc[kp][cq]);
                float h0 = fmaxf(v.x + bb, 0.0f);
                float h1 = fmaxf(v.y + bb, 0.0f);
                float q0 = smask[k0 + 2 * kp] ? h0 : -1e8f;
                float q1 = smask[k0 + 2 * kp + 1] ? h1 : -1e8f;
                m = fmaxf(m, fmaxf(q0, q1));
            }
            mres[half * 4 + cq] = m;
        }
    }
    __syncthreads();  // all act reads done; alias pmax onto act
    {
        int base = (w * 2 + ksub) * 128 + cL * 8;
#pragma unroll
        for (int q = 0; q < 8; q++) pmax[base + q] = mres[q];
    }
    __syncthreads();
    if (t < 128) {
        float m = pmax[t];
#pragma unroll
        for (int q = 1; q < 8; q++) m = fmaxf(m, pmax[q * 128 + t]);
        out[g * 128 + t] = m;
    }
}

// ---------------- launch ----------------
extern "C" void kernel_launch(void* const* d_in, const int* in_sizes, int n_in,
                              void* d_out, int out_size) {
    (void)in_sizes; (void)n_in; (void)out_size;
    const float* x = (const float*)d_in[0];
    const float* pos = (const float*)d_in[1];
    const float* W0 = (const float*)d_in[2];
    const float* b0 = (const float*)d_in[3];
    const float* gg0 = (const float*)d_in[4];
    const float* be0 = (const float*)d_in[5];
    const float* rm0 = (const float*)d_in[6];
    const float* rv0 = (const float*)d_in[7];
    const float* W1 = (const float*)d_in[8];
    const float* b1 = (const float*)d_in[9];
    const float* gg1 = (const float*)d_in[10];
    const float* be1 = (const float*)d_in[11];
    const float* rm1 = (const float*)d_in[12];
    const float* rv1 = (const float*)d_in[13];
    const float* W2 = (const float*)d_in[14];
    const float* b2 = (const float*)d_in[15];
    const float* gg2 = (const float*)d_in[16];
    const float* be2 = (const float*)d_in[17];
    const float* rm2 = (const float*)d_in[18];
    const float* rv2 = (const float*)d_in[19];

    float* out = (float*)d_out;
    float* sampled = out + (size_t)BZf * NSf * 128;

    const int pk_smem = 4096 * 4 + 4096 * 8 + 32;   // 49184 (knn superset of precA)
    const int mlp_smem = (64 * AKS + 4096 + 64 + 128 + 64 * 5) * 4;  // 35840
    const int fps_smem = Nf * 3 * 4 + 2 * 32 * 8;   // 49664
    cudaFuncSetAttribute(pk_kernel, cudaFuncAttributeMaxDynamicSharedMemorySize, pk_smem);
    cudaFuncSetAttribute(mlp_kernel, cudaFuncAttributeMaxDynamicSharedMemorySize, mlp_smem);
    cudaFuncSetAttribute(fps_kernel, cudaFuncAttributeMaxDynamicSharedMemorySize, fps_smem);

    prep_kernel<<<64, 256>>>(pos,
                             W0, b0, gg0, be0, rm0, rv0,
                             W1, b1, gg1, be1, rm1, rv1,
                             W2, b2, gg2, be2, rm2, rv2);
    fps_kernel<<<BZf, 1024, fps_smem>>>(pos, sampled);
    pk_kernel<<<PKA + BZf * NSf, 256, pk_smem>>>(x, pos, sampled);
    mlp_kernel<<<BZf * NSf, 128, mlp_smem>>>(pos, sampled, out);
}